// round 12
// baseline (speedup 1.0000x reference)
#include <cuda_runtime.h>
#include <cuda_fp16.h>
#include <cstdint>

#define BZ   256
#define SRCN 1024
#define DIM  512
#define CHUNKS 8
#define BPC   (BZ / CHUNKS)     // 32 batches per chunk

// ---------------------------------------------------------------------------
// scratch (no cudaMalloc allowed)
// ---------------------------------------------------------------------------
__device__ __align__(16) __half g_src16[(size_t)BZ * SRCN * DIM];   // 268 MB
__device__ __align__(16) __half g_w16[1024 * DIM];                  // W_ref 0-511, conv_w 512-1023
__device__ __align__(16) float  g_q_buf[BZ * DIM];
__device__ __align__(16) float  g_u_part[(size_t)BZ * SRCN * 8];    // 8 partials per (b,s)

// ---------------------------------------------------------------------------
// helpers
// ---------------------------------------------------------------------------
__device__ __forceinline__ uint32_t smem_u32(const void* p) {
    uint32_t a;
    asm("{ .reg .u64 t; cvta.to.shared.u64 t, %1; cvt.u32.u64 %0, t; }" : "=r"(a) : "l"(p));
    return a;
}

#define CP_ASYNC16(dst, src) \
    asm volatile("cp.async.cg.shared.global [%0], [%1], 16;" :: "r"(dst), "l"(src))
#define CP_COMMIT() asm volatile("cp.async.commit_group;" ::: "memory")
#define CP_WAIT1()  asm volatile("cp.async.wait_group 1;" ::: "memory")

__device__ __forceinline__ void ldsm4(uint32_t& r0, uint32_t& r1, uint32_t& r2, uint32_t& r3,
                                      uint32_t addr) {
    asm volatile("ldmatrix.sync.aligned.m8n8.x4.shared.b16 {%0,%1,%2,%3}, [%4];"
                 : "=r"(r0), "=r"(r1), "=r"(r2), "=r"(r3) : "r"(addr));
}

__device__ __forceinline__ void mma_f16(float* c, uint32_t a0, uint32_t a1, uint32_t a2, uint32_t a3,
                                        uint32_t b0, uint32_t b1) {
    asm volatile("mma.sync.aligned.m16n8k16.row.col.f32.f16.f16.f32 "
                 "{%0,%1,%2,%3}, {%4,%5,%6,%7}, {%8,%9}, {%0,%1,%2,%3};"
                 : "+f"(c[0]), "+f"(c[1]), "+f"(c[2]), "+f"(c[3])
                 : "r"(a0), "r"(a1), "r"(a2), "r"(a3), "r"(b0), "r"(b1));
}

__device__ __forceinline__ float ftanh(float x) {
    float e = __expf(2.0f * x);
    return 1.0f - __fdividef(2.0f, e + 1.0f);
}

__device__ __forceinline__ void cvt_store8(const float4* s4, uint2* d2) {
    float4 x[8];
#pragma unroll
    for (int i = 0; i < 8; i++) x[i] = s4[i * 256];
#pragma unroll
    for (int i = 0; i < 8; i++) {
        __half2 h0 = __floats2half2_rn(x[i].x, x[i].y);
        __half2 h1 = __floats2half2_rn(x[i].z, x[i].w);
        d2[i * 256] = make_uint2(*(uint32_t*)&h0, *(uint32_t*)&h1);
    }
}

// ---------------------------------------------------------------------------
// fused prologue: conv src chunk 0 + convert weights + qproj, one launch
// blocks [0,8192): src chunk0; [8192,8448): weights; [8448,8512): qproj
// ---------------------------------------------------------------------------
#define W_ELEMS     (512 * 512)
#define CHUNK_ELEMS ((size_t)BPC * SRCN * DIM)   // 16777216
#define CONV0_BLKS  ((int)(CHUNK_ELEMS / 8 / 256))   // 8192
#define W_BLKS      256
#define QP_BLKS     64

__global__ void __launch_bounds__(256) prologue_kernel(const float* __restrict__ src,
                                                       const float* __restrict__ W_ref,
                                                       const float* __restrict__ conv_w,
                                                       const float* __restrict__ tgt,
                                                       const float* __restrict__ Wq) {
    const int bid = blockIdx.x;
    const int tid = threadIdx.x;

    if (bid < CONV0_BLKS) {
        size_t i8 = ((size_t)bid * 256 + tid) * 8;
        float4 x0 = *reinterpret_cast<const float4*>(src + i8);
        float4 x1 = *reinterpret_cast<const float4*>(src + i8 + 4);
        __half2 h0 = __floats2half2_rn(x0.x, x0.y);
        __half2 h1 = __floats2half2_rn(x0.z, x0.w);
        __half2 h2 = __floats2half2_rn(x1.x, x1.y);
        __half2 h3 = __floats2half2_rn(x1.z, x1.w);
        uint4 o = make_uint4(*(uint32_t*)&h0, *(uint32_t*)&h1, *(uint32_t*)&h2, *(uint32_t*)&h3);
        *reinterpret_cast<uint4*>(g_src16 + i8) = o;
    } else if (bid < CONV0_BLKS + W_BLKS) {
        size_t w8 = (((size_t)(bid - CONV0_BLKS)) * 256 + tid) * 8;
        const float* wsrc = (w8 < W_ELEMS) ? (W_ref + w8) : (conv_w + (w8 - W_ELEMS));
        float4 x0 = *reinterpret_cast<const float4*>(wsrc);
        float4 x1 = *reinterpret_cast<const float4*>(wsrc + 4);
        __half2 h0 = __floats2half2_rn(x0.x, x0.y);
        __half2 h1 = __floats2half2_rn(x0.z, x0.w);
        __half2 h2 = __floats2half2_rn(x1.x, x1.y);
        __half2 h3 = __floats2half2_rn(x1.z, x1.w);
        uint4 o = make_uint4(*(uint32_t*)&h0, *(uint32_t*)&h1, *(uint32_t*)&h2, *(uint32_t*)&h3);
        *reinterpret_cast<uint4*>(g_w16 + w8) = o;
    } else {
        // qproj: 4 batches per block, each thread handles e=tid and e=tid+256
        __shared__ float st[4 * DIM];
        const int b0 = (bid - CONV0_BLKS - W_BLKS) * 4;
        for (int i = tid; i < 4 * DIM; i += 256) st[i] = tgt[(size_t)b0 * DIM + i];
        __syncthreads();
#pragma unroll
        for (int half = 0; half < 2; half++) {
            const int e = tid + half * 256;
            const float4* w = reinterpret_cast<const float4*>(Wq + (size_t)e * DIM);
            float a0 = 0.f, a1 = 0.f, a2 = 0.f, a3 = 0.f;
            const float4* t0 = reinterpret_cast<const float4*>(st);
            const float4* t1 = reinterpret_cast<const float4*>(st + DIM);
            const float4* t2 = reinterpret_cast<const float4*>(st + 2 * DIM);
            const float4* t3 = reinterpret_cast<const float4*>(st + 3 * DIM);
#pragma unroll 4
            for (int i = 0; i < DIM / 4; i++) {
                float4 wv = w[i];
                float4 c;
                c = t0[i]; a0 += wv.x*c.x + wv.y*c.y + wv.z*c.z + wv.w*c.w;
                c = t1[i]; a1 += wv.x*c.x + wv.y*c.y + wv.z*c.z + wv.w*c.w;
                c = t2[i]; a2 += wv.x*c.x + wv.y*c.y + wv.z*c.z + wv.w*c.w;
                c = t3[i]; a3 += wv.x*c.x + wv.y*c.y + wv.z*c.z + wv.w*c.w;
            }
            g_q_buf[(size_t)(b0 + 0) * DIM + e] = a0;
            g_q_buf[(size_t)(b0 + 1) * DIM + e] = a1;
            g_q_buf[(size_t)(b0 + 2) * DIM + e] = a2;
            g_q_buf[(size_t)(b0 + 3) * DIM + e] = a3;
        }
    }
}

// ---------------------------------------------------------------------------
// main GEMM (R5 mainloop): per CTA 128(M=s) x 128(N=e/o), K=512
// K-tile 64, 3 stages of 32KB, 2 CTAs/SM.
// Prelude: fully-unrolled convert of NEXT chunk's src slice.
// grid: (64, BPC): y = batch within chunk, x = nt*8 + mt
// ---------------------------------------------------------------------------
#define KT          64
#define NKT         8
#define STAGES      3
#define STAGE_BYTES 32768
#define C_PITCH     132
#define SM_QV       (STAGES * STAGE_BYTES)       // 98304
#define SMEM_TOTAL  (SM_QV + 1024)               // 99328

extern __shared__ char dsm[];

__global__ void __launch_bounds__(256, 2)
gemm_kernel(const float* __restrict__ conv_b,
            const float* __restrict__ v,
            const float* __restrict__ src32,
            float* __restrict__ out_attn,
            int b_off, int conv_chunk) {
    const uint32_t smb = smem_u32(dsm);
    const int tid  = threadIdx.x;
    const int wid  = tid >> 5;
    const int lane = tid & 31;
    const int wm   = wid & 3;
    const int wn   = wid >> 2;

    const int b  = b_off + blockIdx.y;
    const int nt = blockIdx.x >> 3;
    const int mt = blockIdx.x & 7;
    const int s0 = mt * 128;
    const int n0 = nt * 128;
    const bool is_ref = (nt < 4);

    float* sQ = reinterpret_cast<float*>(dsm + SM_QV);
    float* sV = reinterpret_cast<float*>(dsm + SM_QV + 512);
    float* sC = reinterpret_cast<float*>(dsm);

    if (tid < 128) {
        if (is_ref) {
            sQ[tid] = g_q_buf[(size_t)b * DIM + n0 + tid];
            sV[tid] = v[n0 + tid];
        } else {
            sQ[tid] = conv_b[(n0 - 512) + tid];
        }
    }

    const __half* gA = g_src16 + ((size_t)b * SRCN + s0) * DIM;
    const __half* gB = g_w16 + (size_t)n0 * DIM;

    const int crow = tid >> 3;
    const int ccol = tid & 7;

    const int a_rl = lane & 15;
    const int a_ch = lane >> 4;
    const int b_rl = (lane & 7) | (((lane >> 4) & 1) << 3);
    const int b_ch = (lane >> 3) & 1;

    const int arow0 = wm * 32 + a_rl;
    const int arow1 = arow0 + 16;
    const int ax0 = arow0 & 7;
    const int ax1 = arow1 & 7;
    const int brow0 = wn * 64 + b_rl;

    auto load_stage = [&](int st, int kt) {
        uint32_t base = smb + st * STAGE_BYTES;
        const __half* ga = gA + kt * KT;
        const __half* gb = gB + kt * KT;
#pragma unroll
        for (int p = 0; p < 4; p++) {
            int r = crow + p * 32;
            int swc = ccol ^ (r & 7);
            CP_ASYNC16(base + r * 128 + swc * 16, ga + (size_t)r * DIM + ccol * 8);
        }
#pragma unroll
        for (int p = 0; p < 4; p++) {
            int r = crow + p * 32;
            int swc = ccol ^ (r & 7);
            CP_ASYNC16(base + 16384 + r * 128 + swc * 16, gb + (size_t)r * DIM + ccol * 8);
        }
    };

    load_stage(0, 0); CP_COMMIT();
    load_stage(1, 1); CP_COMMIT();

    // ---- convert prelude: next chunk's src slice, all loads in flight ----
    if (conv_chunk >= 0) {
        const int cta = blockIdx.y * 64 + blockIdx.x;     // 0..2047
        size_t f4base = ((size_t)conv_chunk * CHUNK_ELEMS >> 2) + (size_t)cta * 2048 + tid;
        cvt_store8(reinterpret_cast<const float4*>(src32) + f4base,
                   reinterpret_cast<uint2*>(g_src16) + f4base);
    }

    float cacc[2][8][4];
#pragma unroll
    for (int i = 0; i < 2; i++)
#pragma unroll
        for (int j = 0; j < 8; j++)
#pragma unroll
            for (int r = 0; r < 4; r++) cacc[i][j][r] = 0.f;

    uint32_t a[2][4];
    uint32_t bb[4][4];

    for (int kt = 0; kt < NKT; kt++) {
        CP_WAIT1();
        __syncthreads();
        if (kt + 2 < NKT) load_stage((kt + 2) % 3, kt + 2);
        CP_COMMIT();

        uint32_t abase = smb + (kt % 3) * STAGE_BYTES;
        uint32_t bbase = abase + 16384;

#pragma unroll
        for (int kk = 0; kk < 4; kk++) {
            {
                int c0 = (kk * 2 + a_ch) ^ ax0;
                ldsm4(a[0][0], a[0][1], a[0][2], a[0][3], abase + arow0 * 128 + c0 * 16);
                int c1 = (kk * 2 + a_ch) ^ ax1;
                ldsm4(a[1][0], a[1][1], a[1][2], a[1][3], abase + arow1 * 128 + c1 * 16);
            }
#pragma unroll
            for (int jj = 0; jj < 4; jj++) {
                int brow = brow0 + jj * 16;
                int c = (kk * 2 + b_ch) ^ (brow & 7);
                ldsm4(bb[jj][0], bb[jj][1], bb[jj][2], bb[jj][3], bbase + brow * 128 + c * 16);
            }
#pragma unroll
            for (int i = 0; i < 2; i++)
#pragma unroll
                for (int j = 0; j < 8; j++) {
                    int jj = j >> 1;
                    if (j & 1)
                        mma_f16(cacc[i][j], a[i][0], a[i][1], a[i][2], a[i][3], bb[jj][2], bb[jj][3]);
                    else
                        mma_f16(cacc[i][j], a[i][0], a[i][1], a[i][2], a[i][3], bb[jj][0], bb[jj][1]);
                }
        }
    }

    // ------------------------- epilogues -------------------------
    if (is_ref) {
        const int q = lane >> 2;
        const int cl = (lane & 3) * 2;
#pragma unroll
        for (int i = 0; i < 2; i++) {
            float p0 = 0.f, p1 = 0.f;
#pragma unroll
            for (int j = 0; j < 8; j++) {
                int el = wn * 64 + j * 8 + cl;
                float v0 = sV[el], v1 = sV[el + 1];
                float q0 = sQ[el], q1 = sQ[el + 1];
                p0 += v0 * ftanh(q0 + cacc[i][j][0]) + v1 * ftanh(q1 + cacc[i][j][1]);
                p1 += v0 * ftanh(q0 + cacc[i][j][2]) + v1 * ftanh(q1 + cacc[i][j][3]);
            }
            p0 += __shfl_xor_sync(0xffffffffu, p0, 1);
            p0 += __shfl_xor_sync(0xffffffffu, p0, 2);
            p1 += __shfl_xor_sync(0xffffffffu, p1, 1);
            p1 += __shfl_xor_sync(0xffffffffu, p1, 2);
            if ((lane & 3) == 0) {
                int r0 = wm * 32 + i * 16 + q;
                size_t idx = (((size_t)b * SRCN + s0 + r0) << 3) + nt * 2 + wn;
                g_u_part[idx] = p0;
                g_u_part[idx + (8ull << 3)] = p1;
            }
        }
    } else {
        const int q = lane >> 2;
        const int cl = (lane & 3) * 2;
        const int o0 = n0 - 512;
        float* outb = out_attn + ((size_t)b * DIM + o0) * SRCN + s0;
#pragma unroll
        for (int h = 0; h < 2; h++) {
            __syncthreads();
            if (wn == h) {
#pragma unroll
                for (int i = 0; i < 2; i++) {
                    int r0 = wm * 32 + i * 16 + q;
#pragma unroll
                    for (int j = 0; j < 8; j++) {
                        int o = j * 8 + cl;
                        sC[o * C_PITCH + r0]           = cacc[i][j][0];
                        sC[(o + 1) * C_PITCH + r0]     = cacc[i][j][1];
                        sC[o * C_PITCH + r0 + 8]       = cacc[i][j][2];
                        sC[(o + 1) * C_PITCH + r0 + 8] = cacc[i][j][3];
                    }
                }
            }
            __syncthreads();
#pragma unroll 2
            for (int it = tid; it < 64 * 32; it += 256) {
                int o = it >> 5;
                int sq = (it & 31) * 4;
                float4 val = *reinterpret_cast<const float4*>(sC + o * C_PITCH + sq);
                float bias = sQ[h * 64 + o];
                val.x += bias; val.y += bias; val.z += bias; val.w += bias;
                *reinterpret_cast<float4*>(outb + (size_t)(h * 64 + o) * SRCN + sq) = val;
            }
        }
    }
}

// ---------------------------------------------------------------------------
// softmax: u = sum(8 partials); score=C*tanh(u); mask; softmax; outputs
// ---------------------------------------------------------------------------
__global__ void softmax_kernel(const uint8_t* __restrict__ mask_in,
                               const int* __restrict__ prev,
                               float* __restrict__ out,
                               int has_logits, int has_mask) {
    __shared__ float red[256];
    const int b = blockIdx.x, tid = threadIdx.x;
    const int p = prev[b];

    float sc[4];
    bool  ms[4];
    float mx = -3.0e38f;
#pragma unroll
    for (int j = 0; j < 4; j++) {
        int s = tid + j * 256;
        const float* up = g_u_part + (((size_t)b * SRCN + s) << 3);
        float u = 0.f;
#pragma unroll
        for (int k = 0; k < 8; k++) u += up[k];
        bool m = (mask_in[(size_t)b * SRCN + s] != 0) || (s == p);
        ms[j] = m;
        float val = m ? -3.0e38f : 10.f * tanhf(u);
        sc[j] = val;
        mx = fmaxf(mx, val);
    }
    red[tid] = mx; __syncthreads();
    for (int o = 128; o > 0; o >>= 1) {
        if (tid < o) red[tid] = fmaxf(red[tid], red[tid + o]);
        __syncthreads();
    }
    mx = red[0];
    __syncthreads();

    float e[4], se = 0.f;
#pragma unroll
    for (int j = 0; j < 4; j++) {
        e[j] = ms[j] ? 0.f : expf(sc[j] - mx);
        se += e[j];
    }
    red[tid] = se; __syncthreads();
    for (int o = 128; o > 0; o >>= 1) {
        if (tid < o) red[tid] += red[tid + o];
        __syncthreads();
    }
    const float inv = 1.f / red[0];

    const size_t attn = (size_t)BZ * DIM * SRCN;
#pragma unroll
    for (int j = 0; j < 4; j++) {
        int s = tid + j * 256;
        if (has_logits) out[attn + (size_t)b * SRCN + s] = e[j] * inv;
        if (has_mask)   out[attn + (size_t)BZ * SRCN + (size_t)b * SRCN + s] = ms[j] ? 1.f : 0.f;
    }
}

// ---------------------------------------------------------------------------
extern "C" void kernel_launch(void* const* d_in, const int* in_sizes, int n_in,
                              void* d_out, int out_size) {
    (void)in_sizes; (void)n_in;
    const float*   src    = (const float*)d_in[0];
    const float*   tgt    = (const float*)d_in[1];
    const uint8_t* mask   = (const uint8_t*)d_in[2];
    const int*     prev   = (const int*)d_in[3];
    const float*   W_q    = (const float*)d_in[4];
    const float*   W_ref  = (const float*)d_in[5];
    const float*   v      = (const float*)d_in[6];
    const float*   conv_w = (const float*)d_in[7];
    const float*   conv_b = (const float*)d_in[8];
    float* out = (float*)d_out;

    const size_t attn = (size_t)BZ * DIM * SRCN;
    const size_t row  = (size_t)BZ * SRCN;
    int has_logits = ((size_t)out_size >= attn + row)     ? 1 : 0;
    int has_mask   = ((size_t)out_size >= attn + 2 * row) ? 1 : 0;

    cudaFuncSetAttribute(gemm_kernel,
                         cudaFuncAttributeMaxDynamicSharedMemorySize, SMEM_TOTAL);

    // fused prologue: chunk-0 convert + weight convert + qproj, one launch
    prologue_kernel<<<CONV0_BLKS + W_BLKS + QP_BLKS, 256>>>(src, W_ref, conv_w, tgt, W_q);

    dim3 grid(64, BPC);
    for (int c = 0; c < CHUNKS; c++) {
        int conv_next = (c + 1 < CHUNKS) ? (c + 1) : -1;
        gemm_kernel<<<grid, 256, SMEM_TOTAL>>>(conv_b, v, src, out, c * BPC, conv_next);
    }

    softmax_kernel<<<BZ, 256>>>(mask, prev, out, has_logits, has_mask);
}

// round 13
// speedup vs baseline: 1.0308x; 1.0308x over previous
#include <cuda_runtime.h>
#include <cuda_fp16.h>
#include <cstdint>

#define BZ   256
#define SRCN 1024
#define DIM  512
#define CHUNKS 4
#define BPC   (BZ / CHUNKS)     // 64 batches per chunk

// ---------------------------------------------------------------------------
// scratch (no cudaMalloc allowed)
// ---------------------------------------------------------------------------
__device__ __align__(16) __half g_src16[(size_t)BZ * SRCN * DIM];   // 268 MB
__device__ __align__(16) __half g_w16[1024 * DIM];                  // W_ref 0-511, conv_w 512-1023
__device__ __align__(16) float  g_q_buf[BZ * DIM];
__device__ __align__(16) float  g_u_part[(size_t)BZ * SRCN * 8];    // 8 partials per (b,s)

// ---------------------------------------------------------------------------
// helpers
// ---------------------------------------------------------------------------
__device__ __forceinline__ uint32_t smem_u32(const void* p) {
    uint32_t a;
    asm("{ .reg .u64 t; cvta.to.shared.u64 t, %1; cvt.u32.u64 %0, t; }" : "=r"(a) : "l"(p));
    return a;
}

#define CP_ASYNC16(dst, src) \
    asm volatile("cp.async.cg.shared.global [%0], [%1], 16;" :: "r"(dst), "l"(src))
#define CP_COMMIT() asm volatile("cp.async.commit_group;" ::: "memory")
#define CP_WAIT1()  asm volatile("cp.async.wait_group 1;" ::: "memory")

__device__ __forceinline__ void ldsm4(uint32_t& r0, uint32_t& r1, uint32_t& r2, uint32_t& r3,
                                      uint32_t addr) {
    asm volatile("ldmatrix.sync.aligned.m8n8.x4.shared.b16 {%0,%1,%2,%3}, [%4];"
                 : "=r"(r0), "=r"(r1), "=r"(r2), "=r"(r3) : "r"(addr));
}

__device__ __forceinline__ void mma_f16(float* c, uint32_t a0, uint32_t a1, uint32_t a2, uint32_t a3,
                                        uint32_t b0, uint32_t b1) {
    asm volatile("mma.sync.aligned.m16n8k16.row.col.f32.f16.f16.f32 "
                 "{%0,%1,%2,%3}, {%4,%5,%6,%7}, {%8,%9}, {%0,%1,%2,%3};"
                 : "+f"(c[0]), "+f"(c[1]), "+f"(c[2]), "+f"(c[3])
                 : "r"(a0), "r"(a1), "r"(a2), "r"(a3), "r"(b0), "r"(b1));
}

__device__ __forceinline__ float ftanh(float x) {
    float e = __expf(2.0f * x);
    return 1.0f - __fdividef(2.0f, e + 1.0f);
}

__device__ __forceinline__ void cvt_store8(const float4* s4, uint2* d2) {
    float4 x[8];
#pragma unroll
    for (int i = 0; i < 8; i++) x[i] = s4[i * 256];
#pragma unroll
    for (int i = 0; i < 8; i++) {
        __half2 h0 = __floats2half2_rn(x[i].x, x[i].y);
        __half2 h1 = __floats2half2_rn(x[i].z, x[i].w);
        d2[i * 256] = make_uint2(*(uint32_t*)&h0, *(uint32_t*)&h1);
    }
}

// ---------------------------------------------------------------------------
// fused prologue: conv src chunk 0 + convert weights + qproj, one launch
// blocks [0,16384): src chunk0; [16384,16640): weights; [16640,16704): qproj
// ---------------------------------------------------------------------------
#define W_ELEMS     (512 * 512)
#define CHUNK_ELEMS ((size_t)BPC * SRCN * DIM)       // 33554432
#define CONV0_BLKS  ((int)(CHUNK_ELEMS / 8 / 256))   // 16384
#define W_BLKS      256
#define QP_BLKS     64

__global__ void __launch_bounds__(256) prologue_kernel(const float* __restrict__ src,
                                                       const float* __restrict__ W_ref,
                                                       const float* __restrict__ conv_w,
                                                       const float* __restrict__ tgt,
                                                       const float* __restrict__ Wq) {
    const int bid = blockIdx.x;
    const int tid = threadIdx.x;

    if (bid < CONV0_BLKS) {
        size_t i8 = ((size_t)bid * 256 + tid) * 8;
        float4 x0 = *reinterpret_cast<const float4*>(src + i8);
        float4 x1 = *reinterpret_cast<const float4*>(src + i8 + 4);
        __half2 h0 = __floats2half2_rn(x0.x, x0.y);
        __half2 h1 = __floats2half2_rn(x0.z, x0.w);
        __half2 h2 = __floats2half2_rn(x1.x, x1.y);
        __half2 h3 = __floats2half2_rn(x1.z, x1.w);
        uint4 o = make_uint4(*(uint32_t*)&h0, *(uint32_t*)&h1, *(uint32_t*)&h2, *(uint32_t*)&h3);
        *reinterpret_cast<uint4*>(g_src16 + i8) = o;
    } else if (bid < CONV0_BLKS + W_BLKS) {
        size_t w8 = (((size_t)(bid - CONV0_BLKS)) * 256 + tid) * 8;
        const float* wsrc = (w8 < W_ELEMS) ? (W_ref + w8) : (conv_w + (w8 - W_ELEMS));
        float4 x0 = *reinterpret_cast<const float4*>(wsrc);
        float4 x1 = *reinterpret_cast<const float4*>(wsrc + 4);
        __half2 h0 = __floats2half2_rn(x0.x, x0.y);
        __half2 h1 = __floats2half2_rn(x0.z, x0.w);
        __half2 h2 = __floats2half2_rn(x1.x, x1.y);
        __half2 h3 = __floats2half2_rn(x1.z, x1.w);
        uint4 o = make_uint4(*(uint32_t*)&h0, *(uint32_t*)&h1, *(uint32_t*)&h2, *(uint32_t*)&h3);
        *reinterpret_cast<uint4*>(g_w16 + w8) = o;
    } else {
        // qproj: 4 batches per block, each thread handles e=tid and e=tid+256
        __shared__ float st[4 * DIM];
        const int b0 = (bid - CONV0_BLKS - W_BLKS) * 4;
        for (int i = tid; i < 4 * DIM; i += 256) st[i] = tgt[(size_t)b0 * DIM + i];
        __syncthreads();
#pragma unroll
        for (int half = 0; half < 2; half++) {
            const int e = tid + half * 256;
            const float4* w = reinterpret_cast<const float4*>(Wq + (size_t)e * DIM);
            float a0 = 0.f, a1 = 0.f, a2 = 0.f, a3 = 0.f;
            const float4* t0 = reinterpret_cast<const float4*>(st);
            const float4* t1 = reinterpret_cast<const float4*>(st + DIM);
            const float4* t2 = reinterpret_cast<const float4*>(st + 2 * DIM);
            const float4* t3 = reinterpret_cast<const float4*>(st + 3 * DIM);
#pragma unroll 4
            for (int i = 0; i < DIM / 4; i++) {
                float4 wv = w[i];
                float4 c;
                c = t0[i]; a0 += wv.x*c.x + wv.y*c.y + wv.z*c.z + wv.w*c.w;
                c = t1[i]; a1 += wv.x*c.x + wv.y*c.y + wv.z*c.z + wv.w*c.w;
                c = t2[i]; a2 += wv.x*c.x + wv.y*c.y + wv.z*c.z + wv.w*c.w;
                c = t3[i]; a3 += wv.x*c.x + wv.y*c.y + wv.z*c.z + wv.w*c.w;
            }
            g_q_buf[(size_t)(b0 + 0) * DIM + e] = a0;
            g_q_buf[(size_t)(b0 + 1) * DIM + e] = a1;
            g_q_buf[(size_t)(b0 + 2) * DIM + e] = a2;
            g_q_buf[(size_t)(b0 + 3) * DIM + e] = a3;
        }
    }
}

// ---------------------------------------------------------------------------
// main GEMM (R5 mainloop): per CTA 128(M=s) x 128(N=e/o), K=512
// K-tile 64, 3 stages of 32KB, 2 CTAs/SM.
// Prelude: fully-unrolled convert of NEXT chunk's src slice.
// grid: (64, BPC): y = batch within chunk, x = nt*8 + mt
// ---------------------------------------------------------------------------
#define KT          64
#define NKT         8
#define STAGES      3
#define STAGE_BYTES 32768
#define C_PITCH     132
#define SM_QV       (STAGES * STAGE_BYTES)       // 98304
#define SMEM_TOTAL  (SM_QV + 1024)               // 99328

extern __shared__ char dsm[];

__global__ void __launch_bounds__(256, 2)
gemm_kernel(const float* __restrict__ conv_b,
            const float* __restrict__ v,
            const float* __restrict__ src32,
            float* __restrict__ out_attn,
            int b_off, int conv_chunk) {
    const uint32_t smb = smem_u32(dsm);
    const int tid  = threadIdx.x;
    const int wid  = tid >> 5;
    const int lane = tid & 31;
    const int wm   = wid & 3;
    const int wn   = wid >> 2;

    const int b  = b_off + blockIdx.y;
    const int nt = blockIdx.x >> 3;
    const int mt = blockIdx.x & 7;
    const int s0 = mt * 128;
    const int n0 = nt * 128;
    const bool is_ref = (nt < 4);

    float* sQ = reinterpret_cast<float*>(dsm + SM_QV);
    float* sV = reinterpret_cast<float*>(dsm + SM_QV + 512);
    float* sC = reinterpret_cast<float*>(dsm);

    if (tid < 128) {
        if (is_ref) {
            sQ[tid] = g_q_buf[(size_t)b * DIM + n0 + tid];
            sV[tid] = v[n0 + tid];
        } else {
            sQ[tid] = conv_b[(n0 - 512) + tid];
        }
    }

    const __half* gA = g_src16 + ((size_t)b * SRCN + s0) * DIM;
    const __half* gB = g_w16 + (size_t)n0 * DIM;

    const int crow = tid >> 3;
    const int ccol = tid & 7;

    const int a_rl = lane & 15;
    const int a_ch = lane >> 4;
    const int b_rl = (lane & 7) | (((lane >> 4) & 1) << 3);
    const int b_ch = (lane >> 3) & 1;

    const int arow0 = wm * 32 + a_rl;
    const int arow1 = arow0 + 16;
    const int ax0 = arow0 & 7;
    const int ax1 = arow1 & 7;
    const int brow0 = wn * 64 + b_rl;

    auto load_stage = [&](int st, int kt) {
        uint32_t base = smb + st * STAGE_BYTES;
        const __half* ga = gA + kt * KT;
        const __half* gb = gB + kt * KT;
#pragma unroll
        for (int p = 0; p < 4; p++) {
            int r = crow + p * 32;
            int swc = ccol ^ (r & 7);
            CP_ASYNC16(base + r * 128 + swc * 16, ga + (size_t)r * DIM + ccol * 8);
        }
#pragma unroll
        for (int p = 0; p < 4; p++) {
            int r = crow + p * 32;
            int swc = ccol ^ (r & 7);
            CP_ASYNC16(base + 16384 + r * 128 + swc * 16, gb + (size_t)r * DIM + ccol * 8);
        }
    };

    load_stage(0, 0); CP_COMMIT();
    load_stage(1, 1); CP_COMMIT();

    // ---- convert prelude: next chunk's src slice, all loads in flight ----
    if (conv_chunk >= 0) {
        const int cta = blockIdx.y * 64 + blockIdx.x;     // 0..4095
        size_t f4base = ((size_t)conv_chunk * CHUNK_ELEMS >> 2) + (size_t)cta * 2048 + tid;
        cvt_store8(reinterpret_cast<const float4*>(src32) + f4base,
                   reinterpret_cast<uint2*>(g_src16) + f4base);
    }

    float cacc[2][8][4];
#pragma unroll
    for (int i = 0; i < 2; i++)
#pragma unroll
        for (int j = 0; j < 8; j++)
#pragma unroll
            for (int r = 0; r < 4; r++) cacc[i][j][r] = 0.f;

    uint32_t a[2][4];
    uint32_t bb[4][4];

    for (int kt = 0; kt < NKT; kt++) {
        CP_WAIT1();
        __syncthreads();
        if (kt + 2 < NKT) load_stage((kt + 2) % 3, kt + 2);
        CP_COMMIT();

        uint32_t abase = smb + (kt % 3) * STAGE_BYTES;
        uint32_t bbase = abase + 16384;

#pragma unroll
        for (int kk = 0; kk < 4; kk++) {
            {
                int c0 = (kk * 2 + a_ch) ^ ax0;
                ldsm4(a[0][0], a[0][1], a[0][2], a[0][3], abase + arow0 * 128 + c0 * 16);
                int c1 = (kk * 2 + a_ch) ^ ax1;
                ldsm4(a[1][0], a[1][1], a[1][2], a[1][3], abase + arow1 * 128 + c1 * 16);
            }
#pragma unroll
            for (int jj = 0; jj < 4; jj++) {
                int brow = brow0 + jj * 16;
                int c = (kk * 2 + b_ch) ^ (brow & 7);
                ldsm4(bb[jj][0], bb[jj][1], bb[jj][2], bb[jj][3], bbase + brow * 128 + c * 16);
            }
#pragma unroll
            for (int i = 0; i < 2; i++)
#pragma unroll
                for (int j = 0; j < 8; j++) {
                    int jj = j >> 1;
                    if (j & 1)
                        mma_f16(cacc[i][j], a[i][0], a[i][1], a[i][2], a[i][3], bb[jj][2], bb[jj][3]);
                    else
                        mma_f16(cacc[i][j], a[i][0], a[i][1], a[i][2], a[i][3], bb[jj][0], bb[jj][1]);
                }
        }
    }

    // ------------------------- epilogues -------------------------
    if (is_ref) {
        const int q = lane >> 2;
        const int cl = (lane & 3) * 2;
#pragma unroll
        for (int i = 0; i < 2; i++) {
            float p0 = 0.f, p1 = 0.f;
#pragma unroll
            for (int j = 0; j < 8; j++) {
                int el = wn * 64 + j * 8 + cl;
                float v0 = sV[el], v1 = sV[el + 1];
                float q0 = sQ[el], q1 = sQ[el + 1];
                p0 += v0 * ftanh(q0 + cacc[i][j][0]) + v1 * ftanh(q1 + cacc[i][j][1]);
                p1 += v0 * ftanh(q0 + cacc[i][j][2]) + v1 * ftanh(q1 + cacc[i][j][3]);
            }
            p0 += __shfl_xor_sync(0xffffffffu, p0, 1);
            p0 += __shfl_xor_sync(0xffffffffu, p0, 2);
            p1 += __shfl_xor_sync(0xffffffffu, p1, 1);
            p1 += __shfl_xor_sync(0xffffffffu, p1, 2);
            if ((lane & 3) == 0) {
                int r0 = wm * 32 + i * 16 + q;
                size_t idx = (((size_t)b * SRCN + s0 + r0) << 3) + nt * 2 + wn;
                g_u_part[idx] = p0;
                g_u_part[idx + (8ull << 3)] = p1;
            }
        }
    } else {
        const int q = lane >> 2;
        const int cl = (lane & 3) * 2;
        const int o0 = n0 - 512;
        float* outb = out_attn + ((size_t)b * DIM + o0) * SRCN + s0;
#pragma unroll
        for (int h = 0; h < 2; h++) {
            __syncthreads();
            if (wn == h) {
#pragma unroll
                for (int i = 0; i < 2; i++) {
                    int r0 = wm * 32 + i * 16 + q;
#pragma unroll
                    for (int j = 0; j < 8; j++) {
                        int o = j * 8 + cl;
                        sC[o * C_PITCH + r0]           = cacc[i][j][0];
                        sC[(o + 1) * C_PITCH + r0]     = cacc[i][j][1];
                        sC[o * C_PITCH + r0 + 8]       = cacc[i][j][2];
                        sC[(o + 1) * C_PITCH + r0 + 8] = cacc[i][j][3];
                    }
                }
            }
            __syncthreads();
#pragma unroll 2
            for (int it = tid; it < 64 * 32; it += 256) {
                int o = it >> 5;
                int sq = (it & 31) * 4;
                float4 val = *reinterpret_cast<const float4*>(sC + o * C_PITCH + sq);
                float bias = sQ[h * 64 + o];
                val.x += bias; val.y += bias; val.z += bias; val.w += bias;
                *reinterpret_cast<float4*>(outb + (size_t)(h * 64 + o) * SRCN + sq) = val;
            }
        }
    }
}

// ---------------------------------------------------------------------------
// softmax: u = sum(8 partials); score=C*tanh(u); mask; softmax; outputs
// ---------------------------------------------------------------------------
__global__ void softmax_kernel(const uint8_t* __restrict__ mask_in,
                               const int* __restrict__ prev,
                               float* __restrict__ out,
                               int has_logits, int has_mask) {
    __shared__ float red[256];
    const int b = blockIdx.x, tid = threadIdx.x;
    const int p = prev[b];

    float sc[4];
    bool  ms[4];
    float mx = -3.0e38f;
#pragma unroll
    for (int j = 0; j < 4; j++) {
        int s = tid + j * 256;
        const float* up = g_u_part + (((size_t)b * SRCN + s) << 3);
        float u = 0.f;
#pragma unroll
        for (int k = 0; k < 8; k++) u += up[k];
        bool m = (mask_in[(size_t)b * SRCN + s] != 0) || (s == p);
        ms[j] = m;
        float val = m ? -3.0e38f : 10.f * tanhf(u);
        sc[j] = val;
        mx = fmaxf(mx, val);
    }
    red[tid] = mx; __syncthreads();
    for (int o = 128; o > 0; o >>= 1) {
        if (tid < o) red[tid] = fmaxf(red[tid], red[tid + o]);
        __syncthreads();
    }
    mx = red[0];
    __syncthreads();

    float e[4], se = 0.f;
#pragma unroll
    for (int j = 0; j < 4; j++) {
        e[j] = ms[j] ? 0.f : expf(sc[j] - mx);
        se += e[j];
    }
    red[tid] = se; __syncthreads();
    for (int o = 128; o > 0; o >>= 1) {
        if (tid < o) red[tid] += red[tid + o];
        __syncthreads();
    }
    const float inv = 1.f / red[0];

    const size_t attn = (size_t)BZ * DIM * SRCN;
#pragma unroll
    for (int j = 0; j < 4; j++) {
        int s = tid + j * 256;
        if (has_logits) out[attn + (size_t)b * SRCN + s] = e[j] * inv;
        if (has_mask)   out[attn + (size_t)BZ * SRCN + (size_t)b * SRCN + s] = ms[j] ? 1.f : 0.f;
    }
}

// ---------------------------------------------------------------------------
extern "C" void kernel_launch(void* const* d_in, const int* in_sizes, int n_in,
                              void* d_out, int out_size) {
    (void)in_sizes; (void)n_in;
    const float*   src    = (const float*)d_in[0];
    const float*   tgt    = (const float*)d_in[1];
    const uint8_t* mask   = (const uint8_t*)d_in[2];
    const int*     prev   = (const int*)d_in[3];
    const float*   W_q    = (const float*)d_in[4];
    const float*   W_ref  = (const float*)d_in[5];
    const float*   v      = (const float*)d_in[6];
    const float*   conv_w = (const float*)d_in[7];
    const float*   conv_b = (const float*)d_in[8];
    float* out = (float*)d_out;

    const size_t attn = (size_t)BZ * DIM * SRCN;
    const size_t row  = (size_t)BZ * SRCN;
    int has_logits = ((size_t)out_size >= attn + row)     ? 1 : 0;
    int has_mask   = ((size_t)out_size >= attn + 2 * row) ? 1 : 0;

    cudaFuncSetAttribute(gemm_kernel,
                         cudaFuncAttributeMaxDynamicSharedMemorySize, SMEM_TOTAL);

    // fused prologue: chunk-0 convert + weight convert + qproj, one launch
    prologue_kernel<<<CONV0_BLKS + W_BLKS + QP_BLKS, 256>>>(src, W_ref, conv_w, tgt, W_q);

    dim3 grid(64, BPC);
    for (int c = 0; c < CHUNKS; c++) {
        int conv_next = (c + 1 < CHUNKS) ? (c + 1) : -1;
        gemm_kernel<<<grid, 256, SMEM_TOTAL>>>(conv_b, v, src, out, c * BPC, conv_next);
    }

    softmax_kernel<<<BZ, 256>>>(mask, prev, out, has_logits, has_mask);
}

// round 14
// speedup vs baseline: 1.0964x; 1.0636x over previous
#include <cuda_runtime.h>
#include <cuda_fp16.h>
#include <cstdint>

#define BZ   256
#define SRCN 1024
#define DIM  512
#define CHUNKS 4
#define BPC   (BZ / CHUNKS)     // 64 batches per chunk

// ---------------------------------------------------------------------------
// scratch (no cudaMalloc allowed)
// ---------------------------------------------------------------------------
__device__ __align__(16) __half g_src16[(size_t)BZ * SRCN * DIM];   // 268 MB
__device__ __align__(16) __half g_w16[1024 * DIM];                  // W_ref 0-511, conv_w 512-1023
__device__ __align__(16) float  g_q_buf[BZ * DIM];
__device__ __align__(16) float  g_u_part[(size_t)BZ * SRCN * 8];    // 8 partials per (b,s)
__device__ int g_cnt[CHUNKS];                                        // prelude completion counters

// ---------------------------------------------------------------------------
// helpers
// ---------------------------------------------------------------------------
__device__ __forceinline__ uint32_t smem_u32(const void* p) {
    uint32_t a;
    asm("{ .reg .u64 t; cvta.to.shared.u64 t, %1; cvt.u32.u64 %0, t; }" : "=r"(a) : "l"(p));
    return a;
}

#define CP_ASYNC16(dst, src) \
    asm volatile("cp.async.cg.shared.global [%0], [%1], 16;" :: "r"(dst), "l"(src))
#define CP_COMMIT() asm volatile("cp.async.commit_group;" ::: "memory")
#define CP_WAIT1()  asm volatile("cp.async.wait_group 1;" ::: "memory")

__device__ __forceinline__ void ldsm4(uint32_t& r0, uint32_t& r1, uint32_t& r2, uint32_t& r3,
                                      uint32_t addr) {
    asm volatile("ldmatrix.sync.aligned.m8n8.x4.shared.b16 {%0,%1,%2,%3}, [%4];"
                 : "=r"(r0), "=r"(r1), "=r"(r2), "=r"(r3) : "r"(addr));
}

__device__ __forceinline__ void mma_f16(float* c, uint32_t a0, uint32_t a1, uint32_t a2, uint32_t a3,
                                        uint32_t b0, uint32_t b1) {
    asm volatile("mma.sync.aligned.m16n8k16.row.col.f32.f16.f16.f32 "
                 "{%0,%1,%2,%3}, {%4,%5,%6,%7}, {%8,%9}, {%0,%1,%2,%3};"
                 : "+f"(c[0]), "+f"(c[1]), "+f"(c[2]), "+f"(c[3])
                 : "r"(a0), "r"(a1), "r"(a2), "r"(a3), "r"(b0), "r"(b1));
}

__device__ __forceinline__ float ftanh(float x) {
    float e = __expf(2.0f * x);
    return 1.0f - __fdividef(2.0f, e + 1.0f);
}

__device__ __forceinline__ void cvt_store8(const float4* s4, uint2* d2) {
    float4 x[8];
#pragma unroll
    for (int i = 0; i < 8; i++) x[i] = s4[i * 256];
#pragma unroll
    for (int i = 0; i < 8; i++) {
        __half2 h0 = __floats2half2_rn(x[i].x, x[i].y);
        __half2 h1 = __floats2half2_rn(x[i].z, x[i].w);
        d2[i * 256] = make_uint2(*(uint32_t*)&h0, *(uint32_t*)&h1);
    }
}

// ---------------------------------------------------------------------------
// prologue kernels (separate launches — measured faster than fused)
// ---------------------------------------------------------------------------
#define W_ELEMS     (512 * 512)
#define CHUNK_ELEMS ((size_t)BPC * SRCN * DIM)   // 33554432

__global__ void __launch_bounds__(256) convert_w_kernel(const float* __restrict__ W_ref,
                                                        const float* __restrict__ conv_w) {
    if (blockIdx.x == 0 && threadIdx.x < CHUNKS) g_cnt[threadIdx.x] = 0;  // reset counters
    size_t w8 = ((size_t)blockIdx.x * 256 + threadIdx.x) * 8;
    const float* wsrc = (w8 < W_ELEMS) ? (W_ref + w8) : (conv_w + (w8 - W_ELEMS));
    float4 x0 = *reinterpret_cast<const float4*>(wsrc);
    float4 x1 = *reinterpret_cast<const float4*>(wsrc + 4);
    __half2 h0 = __floats2half2_rn(x0.x, x0.y);
    __half2 h1 = __floats2half2_rn(x0.z, x0.w);
    __half2 h2 = __floats2half2_rn(x1.x, x1.y);
    __half2 h3 = __floats2half2_rn(x1.z, x1.w);
    uint4 o = make_uint4(*(uint32_t*)&h0, *(uint32_t*)&h1, *(uint32_t*)&h2, *(uint32_t*)&h3);
    *reinterpret_cast<uint4*>(g_w16 + w8) = o;
}

__global__ void __launch_bounds__(256) convert_src_kernel(const float* __restrict__ src) {
    size_t i8 = ((size_t)blockIdx.x * 256 + threadIdx.x) * 8;
    float4 x0 = *reinterpret_cast<const float4*>(src + i8);
    float4 x1 = *reinterpret_cast<const float4*>(src + i8 + 4);
    __half2 h0 = __floats2half2_rn(x0.x, x0.y);
    __half2 h1 = __floats2half2_rn(x0.z, x0.w);
    __half2 h2 = __floats2half2_rn(x1.x, x1.y);
    __half2 h3 = __floats2half2_rn(x1.z, x1.w);
    uint4 o = make_uint4(*(uint32_t*)&h0, *(uint32_t*)&h1, *(uint32_t*)&h2, *(uint32_t*)&h3);
    *reinterpret_cast<uint4*>(g_src16 + i8) = o;
}

__global__ void __launch_bounds__(512) qproj_kernel(const float* __restrict__ tgt,
                                                    const float* __restrict__ Wq) {
    __shared__ float st[4 * DIM];
    const int b0 = blockIdx.x * 4;
    const int tid = threadIdx.x;
    for (int i = tid; i < 4 * DIM; i += 512) st[i] = tgt[(size_t)b0 * DIM + i];
    __syncthreads();
    const float4* w = reinterpret_cast<const float4*>(Wq + (size_t)tid * DIM);
    const float4* t0 = reinterpret_cast<const float4*>(st);
    const float4* t1 = reinterpret_cast<const float4*>(st + DIM);
    const float4* t2 = reinterpret_cast<const float4*>(st + 2 * DIM);
    const float4* t3 = reinterpret_cast<const float4*>(st + 3 * DIM);
    float a0 = 0.f, a1 = 0.f, a2 = 0.f, a3 = 0.f;
#pragma unroll 4
    for (int i = 0; i < DIM / 4; i++) {
        float4 wv = w[i];
        float4 c;
        c = t0[i]; a0 += wv.x*c.x + wv.y*c.y + wv.z*c.z + wv.w*c.w;
        c = t1[i]; a1 += wv.x*c.x + wv.y*c.y + wv.z*c.z + wv.w*c.w;
        c = t2[i]; a2 += wv.x*c.x + wv.y*c.y + wv.z*c.z + wv.w*c.w;
        c = t3[i]; a3 += wv.x*c.x + wv.y*c.y + wv.z*c.z + wv.w*c.w;
    }
    g_q_buf[(size_t)(b0 + 0) * DIM + tid] = a0;
    g_q_buf[(size_t)(b0 + 1) * DIM + tid] = a1;
    g_q_buf[(size_t)(b0 + 2) * DIM + tid] = a2;
    g_q_buf[(size_t)(b0 + 3) * DIM + tid] = a3;
}

// ---------------------------------------------------------------------------
// monolithic GEMM with in-kernel chunk gating.
// grid (64, 256): y = global batch, x = nt*8 + mt. bid = x + 64y monotonic:
// all chunk-c CTAs dispatch before chunk-c+1.
// Each CTA: prelude-convert chunk c+1 slice -> fence -> count; then (c>0)
// wait g_cnt[c]==4096 (timeout -> idempotent self-convert fallback);
// then R5 mainloop.
// ---------------------------------------------------------------------------
#define KT          64
#define NKT         8
#define STAGES      3
#define STAGE_BYTES 32768
#define C_PITCH     132
#define SM_QV       (STAGES * STAGE_BYTES)       // 98304
#define SM_FLAG     (SM_QV + 1024)
#define SMEM_TOTAL  (SM_FLAG + 16)               // 99344
#define CTAS_PER_CHUNK 4096

extern __shared__ char dsm[];

__global__ void __launch_bounds__(256, 2)
gemm_kernel(const float* __restrict__ conv_b,
            const float* __restrict__ v,
            const float* __restrict__ src32,
            float* __restrict__ out_attn) {
    const uint32_t smb = smem_u32(dsm);
    const int tid  = threadIdx.x;
    const int wid  = tid >> 5;
    const int lane = tid & 31;
    const int wm   = wid & 3;
    const int wn   = wid >> 2;

    const int b  = blockIdx.y;
    const int chunk = b >> 6;              // BPC = 64
    const int nt = blockIdx.x >> 3;
    const int mt = blockIdx.x & 7;
    const int s0 = mt * 128;
    const int n0 = nt * 128;
    const bool is_ref = (nt < 4);

    float* sQ = reinterpret_cast<float*>(dsm + SM_QV);
    float* sV = reinterpret_cast<float*>(dsm + SM_QV + 512);
    float* sC = reinterpret_cast<float*>(dsm);
    int*  sFlag = reinterpret_cast<int*>(dsm + SM_FLAG);

    if (tid < 128) {
        if (is_ref) {
            sQ[tid] = g_q_buf[(size_t)b * DIM + n0 + tid];
            sV[tid] = v[n0 + tid];
        } else {
            sQ[tid] = conv_b[(n0 - 512) + tid];
        }
    }

    // ---- prelude: convert slice of chunk+1, then signal ----
    if (chunk + 1 < CHUNKS) {
        const int cta_local = (b & 63) * 64 + blockIdx.x;    // 0..4095
        size_t f4base = ((size_t)(chunk + 1) * CHUNK_ELEMS >> 2) + (size_t)cta_local * 2048 + tid;
        cvt_store8(reinterpret_cast<const float4*>(src32) + f4base,
                   reinterpret_cast<uint2*>(g_src16) + f4base);
        __threadfence();
        __syncthreads();
        if (tid == 0) atomicAdd(&g_cnt[chunk + 1], 1);
    }

    // ---- gate: wait for this chunk's data (chunk 0 ready via prologue) ----
    if (chunk > 0) {
        if (tid == 0) {
            int spins = 0, done = 0;
            while (spins < 16384) {
                if (atomicAdd(&g_cnt[chunk], 0) >= CTAS_PER_CHUNK) { done = 1; break; }
                spins++;
            }
            sFlag[0] = done;
        }
        __syncthreads();
        if (!sFlag[0]) {
            // fallback: convert our own A region (idempotent — same values)
            size_t f4 = (((size_t)b * SRCN + s0) * DIM) >> 2;   // 16384 float4
            const float4* s4 = reinterpret_cast<const float4*>(src32) + f4 + tid;
            uint2* d2 = reinterpret_cast<uint2*>(g_src16) + f4 + tid;
#pragma unroll 1
            for (int blk = 0; blk < 8; blk++)
                cvt_store8(s4 + blk * 2048, d2 + blk * 2048);
            __threadfence();
            __syncthreads();
        }
    }

    const __half* gA = g_src16 + ((size_t)b * SRCN + s0) * DIM;
    const __half* gB = g_w16 + (size_t)n0 * DIM;

    const int crow = tid >> 3;
    const int ccol = tid & 7;

    const int a_rl = lane & 15;
    const int a_ch = lane >> 4;
    const int b_rl = (lane & 7) | (((lane >> 4) & 1) << 3);
    const int b_ch = (lane >> 3) & 1;

    const int arow0 = wm * 32 + a_rl;
    const int arow1 = arow0 + 16;
    const int ax0 = arow0 & 7;
    const int ax1 = arow1 & 7;
    const int brow0 = wn * 64 + b_rl;

    auto load_stage = [&](int st, int kt) {
        uint32_t base = smb + st * STAGE_BYTES;
        const __half* ga = gA + kt * KT;
        const __half* gb = gB + kt * KT;
#pragma unroll
        for (int p = 0; p < 4; p++) {
            int r = crow + p * 32;
            int swc = ccol ^ (r & 7);
            CP_ASYNC16(base + r * 128 + swc * 16, ga + (size_t)r * DIM + ccol * 8);
        }
#pragma unroll
        for (int p = 0; p < 4; p++) {
            int r = crow + p * 32;
            int swc = ccol ^ (r & 7);
            CP_ASYNC16(base + 16384 + r * 128 + swc * 16, gb + (size_t)r * DIM + ccol * 8);
        }
    };

    load_stage(0, 0); CP_COMMIT();
    load_stage(1, 1); CP_COMMIT();

    float cacc[2][8][4];
#pragma unroll
    for (int i = 0; i < 2; i++)
#pragma unroll
        for (int j = 0; j < 8; j++)
#pragma unroll
            for (int r = 0; r < 4; r++) cacc[i][j][r] = 0.f;

    uint32_t a[2][4];
    uint32_t bb[4][4];

    for (int kt = 0; kt < NKT; kt++) {
        CP_WAIT1();
        __syncthreads();
        if (kt + 2 < NKT) load_stage((kt + 2) % 3, kt + 2);
        CP_COMMIT();

        uint32_t abase = smb + (kt % 3) * STAGE_BYTES;
        uint32_t bbase = abase + 16384;

#pragma unroll
        for (int kk = 0; kk < 4; kk++) {
            {
                int c0 = (kk * 2 + a_ch) ^ ax0;
                ldsm4(a[0][0], a[0][1], a[0][2], a[0][3], abase + arow0 * 128 + c0 * 16);
                int c1 = (kk * 2 + a_ch) ^ ax1;
                ldsm4(a[1][0], a[1][1], a[1][2], a[1][3], abase + arow1 * 128 + c1 * 16);
            }
#pragma unroll
            for (int jj = 0; jj < 4; jj++) {
                int brow = brow0 + jj * 16;
                int c = (kk * 2 + b_ch) ^ (brow & 7);
                ldsm4(bb[jj][0], bb[jj][1], bb[jj][2], bb[jj][3], bbase + brow * 128 + c * 16);
            }
#pragma unroll
            for (int i = 0; i < 2; i++)
#pragma unroll
                for (int j = 0; j < 8; j++) {
                    int jj = j >> 1;
                    if (j & 1)
                        mma_f16(cacc[i][j], a[i][0], a[i][1], a[i][2], a[i][3], bb[jj][2], bb[jj][3]);
                    else
                        mma_f16(cacc[i][j], a[i][0], a[i][1], a[i][2], a[i][3], bb[jj][0], bb[jj][1]);
                }
        }
    }

    // ------------------------- epilogues -------------------------
    if (is_ref) {
        const int q = lane >> 2;
        const int cl = (lane & 3) * 2;
#pragma unroll
        for (int i = 0; i < 2; i++) {
            float p0 = 0.f, p1 = 0.f;
#pragma unroll
            for (int j = 0; j < 8; j++) {
                int el = wn * 64 + j * 8 + cl;
                float v0 = sV[el], v1 = sV[el + 1];
                float q0 = sQ[el], q1 = sQ[el + 1];
                p0 += v0 * ftanh(q0 + cacc[i][j][0]) + v1 * ftanh(q1 + cacc[i][j][1]);
                p1 += v0 * ftanh(q0 + cacc[i][j][2]) + v1 * ftanh(q1 + cacc[i][j][3]);
            }
            p0 += __shfl_xor_sync(0xffffffffu, p0, 1);
            p0 += __shfl_xor_sync(0xffffffffu, p0, 2);
            p1 += __shfl_xor_sync(0xffffffffu, p1, 1);
            p1 += __shfl_xor_sync(0xffffffffu, p1, 2);
            if ((lane & 3) == 0) {
                int r0 = wm * 32 + i * 16 + q;
                size_t idx = (((size_t)b * SRCN + s0 + r0) << 3) + nt * 2 + wn;
                g_u_part[idx] = p0;
                g_u_part[idx + (8ull << 3)] = p1;
            }
        }
    } else {
        const int q = lane >> 2;
        const int cl = (lane & 3) * 2;
        const int o0 = n0 - 512;
        float* outb = out_attn + ((size_t)b * DIM + o0) * SRCN + s0;
#pragma unroll
        for (int h = 0; h < 2; h++) {
            __syncthreads();
            if (wn == h) {
#pragma unroll
                for (int i = 0; i < 2; i++) {
                    int r0 = wm * 32 + i * 16 + q;
#pragma unroll
                    for (int j = 0; j < 8; j++) {
                        int o = j * 8 + cl;
                        sC[o * C_PITCH + r0]           = cacc[i][j][0];
                        sC[(o + 1) * C_PITCH + r0]     = cacc[i][j][1];
                        sC[o * C_PITCH + r0 + 8]       = cacc[i][j][2];
                        sC[(o + 1) * C_PITCH + r0 + 8] = cacc[i][j][3];
                    }
                }
            }
            __syncthreads();
#pragma unroll 2
            for (int it = tid; it < 64 * 32; it += 256) {
                int o = it >> 5;
                int sq = (it & 31) * 4;
                float4 val = *reinterpret_cast<const float4*>(sC + o * C_PITCH + sq);
                float bias = sQ[h * 64 + o];
                val.x += bias; val.y += bias; val.z += bias; val.w += bias;
                *reinterpret_cast<float4*>(outb + (size_t)(h * 64 + o) * SRCN + sq) = val;
            }
        }
    }
}

// ---------------------------------------------------------------------------
// softmax: u = sum(8 partials); score=C*tanh(u); mask; softmax; outputs
// ---------------------------------------------------------------------------
__global__ void softmax_kernel(const uint8_t* __restrict__ mask_in,
                               const int* __restrict__ prev,
                               float* __restrict__ out,
                               int has_logits, int has_mask) {
    __shared__ float red[256];
    const int b = blockIdx.x, tid = threadIdx.x;
    const int p = prev[b];

    float sc[4];
    bool  ms[4];
    float mx = -3.0e38f;
#pragma unroll
    for (int j = 0; j < 4; j++) {
        int s = tid + j * 256;
        const float* up = g_u_part + (((size_t)b * SRCN + s) << 3);
        float u = 0.f;
#pragma unroll
        for (int k = 0; k < 8; k++) u += up[k];
        bool m = (mask_in[(size_t)b * SRCN + s] != 0) || (s == p);
        ms[j] = m;
        float val = m ? -3.0e38f : 10.f * tanhf(u);
        sc[j] = val;
        mx = fmaxf(mx, val);
    }
    red[tid] = mx; __syncthreads();
    for (int o = 128; o > 0; o >>= 1) {
        if (tid < o) red[tid] = fmaxf(red[tid], red[tid + o]);
        __syncthreads();
    }
    mx = red[0];
    __syncthreads();

    float e[4], se = 0.f;
#pragma unroll
    for (int j = 0; j < 4; j++) {
        e[j] = ms[j] ? 0.f : expf(sc[j] - mx);
        se += e[j];
    }
    red[tid] = se; __syncthreads();
    for (int o = 128; o > 0; o >>= 1) {
        if (tid < o) red[tid] += red[tid + o];
        __syncthreads();
    }
    const float inv = 1.f / red[0];

    const size_t attn = (size_t)BZ * DIM * SRCN;
#pragma unroll
    for (int j = 0; j < 4; j++) {
        int s = tid + j * 256;
        if (has_logits) out[attn + (size_t)b * SRCN + s] = e[j] * inv;
        if (has_mask)   out[attn + (size_t)BZ * SRCN + (size_t)b * SRCN + s] = ms[j] ? 1.f : 0.f;
    }
}

// ---------------------------------------------------------------------------
extern "C" void kernel_launch(void* const* d_in, const int* in_sizes, int n_in,
                              void* d_out, int out_size) {
    (void)in_sizes; (void)n_in;
    const float*   src    = (const float*)d_in[0];
    const float*   tgt    = (const float*)d_in[1];
    const uint8_t* mask   = (const uint8_t*)d_in[2];
    const int*     prev   = (const int*)d_in[3];
    const float*   W_q    = (const float*)d_in[4];
    const float*   W_ref  = (const float*)d_in[5];
    const float*   v      = (const float*)d_in[6];
    const float*   conv_w = (const float*)d_in[7];
    const float*   conv_b = (const float*)d_in[8];
    float* out = (float*)d_out;

    const size_t attn = (size_t)BZ * DIM * SRCN;
    const size_t row  = (size_t)BZ * SRCN;
    int has_logits = ((size_t)out_size >= attn + row)     ? 1 : 0;
    int has_mask   = ((size_t)out_size >= attn + 2 * row) ? 1 : 0;

    cudaFuncSetAttribute(gemm_kernel,
                         cudaFuncAttributeMaxDynamicSharedMemorySize, SMEM_TOTAL);

    // prologue: counter reset + weight convert, qproj, chunk-0 src convert
    convert_w_kernel<<<256, 256>>>(W_ref, conv_w);
    qproj_kernel<<<64, 512>>>(tgt, W_q);
    convert_src_kernel<<<(int)(CHUNK_ELEMS / 8 / 256), 256>>>(src);

    // single monolithic GEMM with in-kernel chunk gating
    dim3 grid(64, BZ);
    gemm_kernel<<<grid, 256, SMEM_TOTAL>>>(conv_b, v, src, out);

    softmax_kernel<<<BZ, 256>>>(mask, prev, out, has_logits, has_mask);
}

// round 15
// speedup vs baseline: 1.0998x; 1.0031x over previous
#include <cuda_runtime.h>
#include <cuda_fp16.h>
#include <cstdint>

#define BZ   256
#define SRCN 1024
#define DIM  512
#define CHUNKS 4
#define BPC   (BZ / CHUNKS)     // 64 batches per chunk

// ---------------------------------------------------------------------------
// scratch (no cudaMalloc allowed)
// ---------------------------------------------------------------------------
__device__ __align__(16) __half g_src16[(size_t)BZ * SRCN * DIM];   // 268 MB
__device__ __align__(16) __half g_w16[1024 * DIM];                  // W_ref 0-511, conv_w 512-1023
__device__ __align__(16) float  g_q_buf[BZ * DIM];
__device__ __align__(16) float  g_u_part[(size_t)BZ * SRCN * 8];    // 8 partials per (b,s)
__device__ int g_cnt[CHUNKS];                                        // prelude completion counters

// ---------------------------------------------------------------------------
// helpers
// ---------------------------------------------------------------------------
__device__ __forceinline__ uint32_t smem_u32(const void* p) {
    uint32_t a;
    asm("{ .reg .u64 t; cvta.to.shared.u64 t, %1; cvt.u32.u64 %0, t; }" : "=r"(a) : "l"(p));
    return a;
}

#define CP_ASYNC16(dst, src) \
    asm volatile("cp.async.cg.shared.global [%0], [%1], 16;" :: "r"(dst), "l"(src))
#define CP_COMMIT() asm volatile("cp.async.commit_group;" ::: "memory")
#define CP_WAIT1()  asm volatile("cp.async.wait_group 1;" ::: "memory")

__device__ __forceinline__ void ldsm4(uint32_t& r0, uint32_t& r1, uint32_t& r2, uint32_t& r3,
                                      uint32_t addr) {
    asm volatile("ldmatrix.sync.aligned.m8n8.x4.shared.b16 {%0,%1,%2,%3}, [%4];"
                 : "=r"(r0), "=r"(r1), "=r"(r2), "=r"(r3) : "r"(addr));
}

__device__ __forceinline__ void mma_f16(float* c, uint32_t a0, uint32_t a1, uint32_t a2, uint32_t a3,
                                        uint32_t b0, uint32_t b1) {
    asm volatile("mma.sync.aligned.m16n8k16.row.col.f32.f16.f16.f32 "
                 "{%0,%1,%2,%3}, {%4,%5,%6,%7}, {%8,%9}, {%0,%1,%2,%3};"
                 : "+f"(c[0]), "+f"(c[1]), "+f"(c[2]), "+f"(c[3])
                 : "r"(a0), "r"(a1), "r"(a2), "r"(a3), "r"(b0), "r"(b1));
}

__device__ __forceinline__ float ftanh(float x) {
    float e = __expf(2.0f * x);
    return 1.0f - __fdividef(2.0f, e + 1.0f);
}

__device__ __forceinline__ void cvt_store8(const float4* s4, uint2* d2) {
    float4 x[8];
#pragma unroll
    for (int i = 0; i < 8; i++) x[i] = s4[i * 256];
#pragma unroll
    for (int i = 0; i < 8; i++) {
        __half2 h0 = __floats2half2_rn(x[i].x, x[i].y);
        __half2 h1 = __floats2half2_rn(x[i].z, x[i].w);
        d2[i * 256] = make_uint2(*(uint32_t*)&h0, *(uint32_t*)&h1);
    }
}

__device__ __forceinline__ int ld_cg(const int* p) {
    int v;
    asm volatile("ld.global.cg.s32 %0, [%1];" : "=r"(v) : "l"(p));
    return v;
}

// ---------------------------------------------------------------------------
// prologue kernels (separate launches — measured faster than fused)
// ---------------------------------------------------------------------------
#define W_ELEMS     (512 * 512)
#define CHUNK_ELEMS ((size_t)BPC * SRCN * DIM)   // 33554432

__global__ void __launch_bounds__(256) convert_w_kernel(const float* __restrict__ W_ref,
                                                        const float* __restrict__ conv_w) {
    if (blockIdx.x == 0 && threadIdx.x < CHUNKS) g_cnt[threadIdx.x] = 0;  // reset counters
    size_t w8 = ((size_t)blockIdx.x * 256 + threadIdx.x) * 8;
    const float* wsrc = (w8 < W_ELEMS) ? (W_ref + w8) : (conv_w + (w8 - W_ELEMS));
    float4 x0 = *reinterpret_cast<const float4*>(wsrc);
    float4 x1 = *reinterpret_cast<const float4*>(wsrc + 4);
    __half2 h0 = __floats2half2_rn(x0.x, x0.y);
    __half2 h1 = __floats2half2_rn(x0.z, x0.w);
    __half2 h2 = __floats2half2_rn(x1.x, x1.y);
    __half2 h3 = __floats2half2_rn(x1.z, x1.w);
    uint4 o = make_uint4(*(uint32_t*)&h0, *(uint32_t*)&h1, *(uint32_t*)&h2, *(uint32_t*)&h3);
    *reinterpret_cast<uint4*>(g_w16 + w8) = o;
}

__global__ void __launch_bounds__(256) convert_src_kernel(const float* __restrict__ src) {
    size_t i8 = ((size_t)blockIdx.x * 256 + threadIdx.x) * 8;
    float4 x0 = *reinterpret_cast<const float4*>(src + i8);
    float4 x1 = *reinterpret_cast<const float4*>(src + i8 + 4);
    __half2 h0 = __floats2half2_rn(x0.x, x0.y);
    __half2 h1 = __floats2half2_rn(x0.z, x0.w);
    __half2 h2 = __floats2half2_rn(x1.x, x1.y);
    __half2 h3 = __floats2half2_rn(x1.z, x1.w);
    uint4 o = make_uint4(*(uint32_t*)&h0, *(uint32_t*)&h1, *(uint32_t*)&h2, *(uint32_t*)&h3);
    *reinterpret_cast<uint4*>(g_src16 + i8) = o;
}

__global__ void __launch_bounds__(512) qproj_kernel(const float* __restrict__ tgt,
                                                    const float* __restrict__ Wq) {
    __shared__ float st[4 * DIM];
    const int b0 = blockIdx.x * 4;
    const int tid = threadIdx.x;
    for (int i = tid; i < 4 * DIM; i += 512) st[i] = tgt[(size_t)b0 * DIM + i];
    __syncthreads();
    const float4* w = reinterpret_cast<const float4*>(Wq + (size_t)tid * DIM);
    const float4* t0 = reinterpret_cast<const float4*>(st);
    const float4* t1 = reinterpret_cast<const float4*>(st + DIM);
    const float4* t2 = reinterpret_cast<const float4*>(st + 2 * DIM);
    const float4* t3 = reinterpret_cast<const float4*>(st + 3 * DIM);
    float a0 = 0.f, a1 = 0.f, a2 = 0.f, a3 = 0.f;
#pragma unroll 4
    for (int i = 0; i < DIM / 4; i++) {
        float4 wv = w[i];
        float4 c;
        c = t0[i]; a0 += wv.x*c.x + wv.y*c.y + wv.z*c.z + wv.w*c.w;
        c = t1[i]; a1 += wv.x*c.x + wv.y*c.y + wv.z*c.z + wv.w*c.w;
        c = t2[i]; a2 += wv.x*c.x + wv.y*c.y + wv.z*c.z + wv.w*c.w;
        c = t3[i]; a3 += wv.x*c.x + wv.y*c.y + wv.z*c.z + wv.w*c.w;
    }
    g_q_buf[(size_t)(b0 + 0) * DIM + tid] = a0;
    g_q_buf[(size_t)(b0 + 1) * DIM + tid] = a1;
    g_q_buf[(size_t)(b0 + 2) * DIM + tid] = a2;
    g_q_buf[(size_t)(b0 + 3) * DIM + tid] = a3;
}

// ---------------------------------------------------------------------------
// monolithic GEMM with in-kernel chunk gating (cheap-poll version).
// grid (64, 256): y = global batch, x = nt*8 + mt. bid monotonic in chunk.
// Prelude: convert chunk c+1 slice -> fence -> atomicAdd.
// Gate: ld.global.cg poll + nanosleep (no atomic spin), fallback idempotent.
// ---------------------------------------------------------------------------
#define KT          64
#define NKT         8
#define STAGES      3
#define STAGE_BYTES 32768
#define C_PITCH     132
#define SM_QV       (STAGES * STAGE_BYTES)       // 98304
#define SM_FLAG     (SM_QV + 1024)
#define SMEM_TOTAL  (SM_FLAG + 16)               // 99344
#define CTAS_PER_CHUNK 4096

extern __shared__ char dsm[];

__global__ void __launch_bounds__(256, 2)
gemm_kernel(const float* __restrict__ conv_b,
            const float* __restrict__ v,
            const float* __restrict__ src32,
            float* __restrict__ out_attn) {
    const uint32_t smb = smem_u32(dsm);
    const int tid  = threadIdx.x;
    const int wid  = tid >> 5;
    const int lane = tid & 31;
    const int wm   = wid & 3;
    const int wn   = wid >> 2;

    const int b  = blockIdx.y;
    const int chunk = b >> 6;              // BPC = 64
    const int nt = blockIdx.x >> 3;
    const int mt = blockIdx.x & 7;
    const int s0 = mt * 128;
    const int n0 = nt * 128;
    const bool is_ref = (nt < 4);

    float* sQ = reinterpret_cast<float*>(dsm + SM_QV);
    float* sV = reinterpret_cast<float*>(dsm + SM_QV + 512);
    float* sC = reinterpret_cast<float*>(dsm);
    int*  sFlag = reinterpret_cast<int*>(dsm + SM_FLAG);

    if (tid < 128) {
        if (is_ref) {
            sQ[tid] = g_q_buf[(size_t)b * DIM + n0 + tid];
            sV[tid] = v[n0 + tid];
        } else {
            sQ[tid] = conv_b[(n0 - 512) + tid];
        }
    }

    // ---- prelude: convert slice of chunk+1, then signal ----
    if (chunk + 1 < CHUNKS) {
        const int cta_local = (b & 63) * 64 + blockIdx.x;    // 0..4095
        size_t f4base = ((size_t)(chunk + 1) * CHUNK_ELEMS >> 2) + (size_t)cta_local * 2048 + tid;
        cvt_store8(reinterpret_cast<const float4*>(src32) + f4base,
                   reinterpret_cast<uint2*>(g_src16) + f4base);
        __threadfence();
        __syncthreads();
        if (tid == 0) atomicAdd(&g_cnt[chunk + 1], 1);
    }

    // ---- gate: wait for this chunk's data (chunk 0 ready via prologue) ----
    if (chunk > 0) {
        if (tid == 0) {
            int done = 0;
            for (int spins = 0; spins < 100000; spins++) {
                if (ld_cg(&g_cnt[chunk]) >= CTAS_PER_CHUNK) { done = 1; break; }
                __nanosleep(200);
            }
            sFlag[0] = done;
        }
        __syncthreads();
        if (!sFlag[0]) {
            // fallback: convert our own A region (idempotent — same values)
            size_t f4 = (((size_t)b * SRCN + s0) * DIM) >> 2;
            const float4* s4 = reinterpret_cast<const float4*>(src32) + f4 + tid;
            uint2* d2 = reinterpret_cast<uint2*>(g_src16) + f4 + tid;
#pragma unroll 1
            for (int blk = 0; blk < 8; blk++)
                cvt_store8(s4 + blk * 2048, d2 + blk * 2048);
            __threadfence();
            __syncthreads();
        }
    }

    const __half* gA = g_src16 + ((size_t)b * SRCN + s0) * DIM;
    const __half* gB = g_w16 + (size_t)n0 * DIM;

    const int crow = tid >> 3;
    const int ccol = tid & 7;

    const int a_rl = lane & 15;
    const int a_ch = lane >> 4;
    const int b_rl = (lane & 7) | (((lane >> 4) & 1) << 3);
    const int b_ch = (lane >> 3) & 1;

    const int arow0 = wm * 32 + a_rl;
    const int arow1 = arow0 + 16;
    const int ax0 = arow0 & 7;
    const int ax1 = arow1 & 7;
    const int brow0 = wn * 64 + b_rl;

    auto load_stage = [&](int st, int kt) {
        uint32_t base = smb + st * STAGE_BYTES;
        const __half* ga = gA + kt * KT;
        const __half* gb = gB + kt * KT;
#pragma unroll
        for (int p = 0; p < 4; p++) {
            int r = crow + p * 32;
            int swc = ccol ^ (r & 7);
            CP_ASYNC16(base + r * 128 + swc * 16, ga + (size_t)r * DIM + ccol * 8);
        }
#pragma unroll
        for (int p = 0; p < 4; p++) {
            int r = crow + p * 32;
            int swc = ccol ^ (r & 7);
            CP_ASYNC16(base + 16384 + r * 128 + swc * 16, gb + (size_t)r * DIM + ccol * 8);
        }
    };

    load_stage(0, 0); CP_COMMIT();
    load_stage(1, 1); CP_COMMIT();

    float cacc[2][8][4];
#pragma unroll
    for (int i = 0; i < 2; i++)
#pragma unroll
        for (int j = 0; j < 8; j++)
#pragma unroll
            for (int r = 0; r < 4; r++) cacc[i][j][r] = 0.f;

    uint32_t a[2][4];
    uint32_t bb[4][4];

    for (int kt = 0; kt < NKT; kt++) {
        CP_WAIT1();
        __syncthreads();
        if (kt + 2 < NKT) load_stage((kt + 2) % 3, kt + 2);
        CP_COMMIT();

        uint32_t abase = smb + (kt % 3) * STAGE_BYTES;
        uint32_t bbase = abase + 16384;

#pragma unroll
        for (int kk = 0; kk < 4; kk++) {
            {
                int c0 = (kk * 2 + a_ch) ^ ax0;
                ldsm4(a[0][0], a[0][1], a[0][2], a[0][3], abase + arow0 * 128 + c0 * 16);
                int c1 = (kk * 2 + a_ch) ^ ax1;
                ldsm4(a[1][0], a[1][1], a[1][2], a[1][3], abase + arow1 * 128 + c1 * 16);
            }
#pragma unroll
            for (int jj = 0; jj < 4; jj++) {
                int brow = brow0 + jj * 16;
                int c = (kk * 2 + b_ch) ^ (brow & 7);
                ldsm4(bb[jj][0], bb[jj][1], bb[jj][2], bb[jj][3], bbase + brow * 128 + c * 16);
            }
#pragma unroll
            for (int i = 0; i < 2; i++)
#pragma unroll
                for (int j = 0; j < 8; j++) {
                    int jj = j >> 1;
                    if (j & 1)
                        mma_f16(cacc[i][j], a[i][0], a[i][1], a[i][2], a[i][3], bb[jj][2], bb[jj][3]);
                    else
                        mma_f16(cacc[i][j], a[i][0], a[i][1], a[i][2], a[i][3], bb[jj][0], bb[jj][1]);
                }
        }
    }

    // ------------------------- epilogues -------------------------
    if (is_ref) {
        const int q = lane >> 2;
        const int cl = (lane & 3) * 2;
#pragma unroll
        for (int i = 0; i < 2; i++) {
            float p0 = 0.f, p1 = 0.f;
#pragma unroll
            for (int j = 0; j < 8; j++) {
                int el = wn * 64 + j * 8 + cl;
                float v0 = sV[el], v1 = sV[el + 1];
                float q0 = sQ[el], q1 = sQ[el + 1];
                p0 += v0 * ftanh(q0 + cacc[i][j][0]) + v1 * ftanh(q1 + cacc[i][j][1]);
                p1 += v0 * ftanh(q0 + cacc[i][j][2]) + v1 * ftanh(q1 + cacc[i][j][3]);
            }
            p0 += __shfl_xor_sync(0xffffffffu, p0, 1);
            p0 += __shfl_xor_sync(0xffffffffu, p0, 2);
            p1 += __shfl_xor_sync(0xffffffffu, p1, 1);
            p1 += __shfl_xor_sync(0xffffffffu, p1, 2);
            if ((lane & 3) == 0) {
                int r0 = wm * 32 + i * 16 + q;
                size_t idx = (((size_t)b * SRCN + s0 + r0) << 3) + nt * 2 + wn;
                g_u_part[idx] = p0;
                g_u_part[idx + (8ull << 3)] = p1;
            }
        }
    } else {
        const int q = lane >> 2;
        const int cl = (lane & 3) * 2;
        const int o0 = n0 - 512;
        float* outb = out_attn + ((size_t)b * DIM + o0) * SRCN + s0;
#pragma unroll
        for (int h = 0; h < 2; h++) {
            __syncthreads();
            if (wn == h) {
#pragma unroll
                for (int i = 0; i < 2; i++) {
                    int r0 = wm * 32 + i * 16 + q;
#pragma unroll
                    for (int j = 0; j < 8; j++) {
                        int o = j * 8 + cl;
                        sC[o * C_PITCH + r0]           = cacc[i][j][0];
                        sC[(o + 1) * C_PITCH + r0]     = cacc[i][j][1];
                        sC[o * C_PITCH + r0 + 8]       = cacc[i][j][2];
                        sC[(o + 1) * C_PITCH + r0 + 8] = cacc[i][j][3];
                    }
                }
            }
            __syncthreads();
#pragma unroll 2
            for (int it = tid; it < 64 * 32; it += 256) {
                int o = it >> 5;
                int sq = (it & 31) * 4;
                float4 val = *reinterpret_cast<const float4*>(sC + o * C_PITCH + sq);
                float bias = sQ[h * 64 + o];
                val.x += bias; val.y += bias; val.z += bias; val.w += bias;
                *reinterpret_cast<float4*>(outb + (size_t)(h * 64 + o) * SRCN + sq) = val;
            }
        }
    }
}

// ---------------------------------------------------------------------------
// softmax: u = sum(8 partials); score=C*tanh(u); mask; softmax; outputs
// ---------------------------------------------------------------------------
__global__ void softmax_kernel(const uint8_t* __restrict__ mask_in,
                               const int* __restrict__ prev,
                               float* __restrict__ out,
                               int has_logits, int has_mask) {
    __shared__ float red[256];
    const int b = blockIdx.x, tid = threadIdx.x;
    const int p = prev[b];

    float sc[4];
    bool  ms[4];
    float mx = -3.0e38f;
#pragma unroll
    for (int j = 0; j < 4; j++) {
        int s = tid + j * 256;
        const float* up = g_u_part + (((size_t)b * SRCN + s) << 3);
        float u = 0.f;
#pragma unroll
        for (int k = 0; k < 8; k++) u += up[k];
        bool m = (mask_in[(size_t)b * SRCN + s] != 0) || (s == p);
        ms[j] = m;
        float val = m ? -3.0e38f : 10.f * tanhf(u);
        sc[j] = val;
        mx = fmaxf(mx, val);
    }
    red[tid] = mx; __syncthreads();
    for (int o = 128; o > 0; o >>= 1) {
        if (tid < o) red[tid] = fmaxf(red[tid], red[tid + o]);
        __syncthreads();
    }
    mx = red[0];
    __syncthreads();

    float e[4], se = 0.f;
#pragma unroll
    for (int j = 0; j < 4; j++) {
        e[j] = ms[j] ? 0.f : expf(sc[j] - mx);
        se += e[j];
    }
    red[tid] = se; __syncthreads();
    for (int o = 128; o > 0; o >>= 1) {
        if (tid < o) red[tid] += red[tid + o];
        __syncthreads();
    }
    const float inv = 1.f / red[0];

    const size_t attn = (size_t)BZ * DIM * SRCN;
#pragma unroll
    for (int j = 0; j < 4; j++) {
        int s = tid + j * 256;
        if (has_logits) out[attn + (size_t)b * SRCN + s] = e[j] * inv;
        if (has_mask)   out[attn + (size_t)BZ * SRCN + (size_t)b * SRCN + s] = ms[j] ? 1.f : 0.f;
    }
}

// ---------------------------------------------------------------------------
extern "C" void kernel_launch(void* const* d_in, const int* in_sizes, int n_in,
                              void* d_out, int out_size) {
    (void)in_sizes; (void)n_in;
    const float*   src    = (const float*)d_in[0];
    const float*   tgt    = (const float*)d_in[1];
    const uint8_t* mask   = (const uint8_t*)d_in[2];
    const int*     prev   = (const int*)d_in[3];
    const float*   W_q    = (const float*)d_in[4];
    const float*   W_ref  = (const float*)d_in[5];
    const float*   v      = (const float*)d_in[6];
    const float*   conv_w = (const float*)d_in[7];
    const float*   conv_b = (const float*)d_in[8];
    float* out = (float*)d_out;

    const size_t attn = (size_t)BZ * DIM * SRCN;
    const size_t row  = (size_t)BZ * SRCN;
    int has_logits = ((size_t)out_size >= attn + row)     ? 1 : 0;
    int has_mask   = ((size_t)out_size >= attn + 2 * row) ? 1 : 0;

    cudaFuncSetAttribute(gemm_kernel,
                         cudaFuncAttributeMaxDynamicSharedMemorySize, SMEM_TOTAL);

    // prologue: counter reset + weight convert, qproj, chunk-0 src convert
    convert_w_kernel<<<256, 256>>>(W_ref, conv_w);
    qproj_kernel<<<64, 512>>>(tgt, W_q);
    convert_src_kernel<<<(int)(CHUNK_ELEMS / 8 / 256), 256>>>(src);

    // single monolithic GEMM with in-kernel chunk gating
    dim3 grid(64, BZ);
    gemm_kernel<<<grid, 256, SMEM_TOTAL>>>(conv_b, v, src, out);

    softmax_kernel<<<BZ, 256>>>(mask, prev, out, has_logits, has_mask);
}

// round 16
// speedup vs baseline: 1.1375x; 1.0343x over previous
#include <cuda_runtime.h>
#include <cuda_fp16.h>
#include <cstdint>

#define BZ   256
#define SRCN 1024
#define DIM  512

// non-uniform chunks: {16, 48, 96, 96} batches
#define C0B 16
#define C1B 48
#define C2B 96
#define C3B 96

// ---------------------------------------------------------------------------
// scratch (no cudaMalloc allowed)
// ---------------------------------------------------------------------------
__device__ __align__(16) __half g_src16[(size_t)BZ * SRCN * DIM];   // 268 MB
__device__ __align__(16) __half g_w16[1024 * DIM];                  // W_ref 0-511, conv_w 512-1023
__device__ __align__(16) float  g_q_buf[BZ * DIM];
__device__ __align__(16) float  g_u_part[(size_t)BZ * SRCN * 8];    // 8 partials per (b,s)

// ---------------------------------------------------------------------------
// helpers
// ---------------------------------------------------------------------------
__device__ __forceinline__ uint32_t smem_u32(const void* p) {
    uint32_t a;
    asm("{ .reg .u64 t; cvta.to.shared.u64 t, %1; cvt.u32.u64 %0, t; }" : "=r"(a) : "l"(p));
    return a;
}

#define CP_ASYNC16(dst, src) \
    asm volatile("cp.async.cg.shared.global [%0], [%1], 16;" :: "r"(dst), "l"(src))
#define CP_COMMIT() asm volatile("cp.async.commit_group;" ::: "memory")
#define CP_WAIT1()  asm volatile("cp.async.wait_group 1;" ::: "memory")

__device__ __forceinline__ void ldsm4(uint32_t& r0, uint32_t& r1, uint32_t& r2, uint32_t& r3,
                                      uint32_t addr) {
    asm volatile("ldmatrix.sync.aligned.m8n8.x4.shared.b16 {%0,%1,%2,%3}, [%4];"
                 : "=r"(r0), "=r"(r1), "=r"(r2), "=r"(r3) : "r"(addr));
}

__device__ __forceinline__ void mma_f16(float* c, uint32_t a0, uint32_t a1, uint32_t a2, uint32_t a3,
                                        uint32_t b0, uint32_t b1) {
    asm volatile("mma.sync.aligned.m16n8k16.row.col.f32.f16.f16.f32 "
                 "{%0,%1,%2,%3}, {%4,%5,%6,%7}, {%8,%9}, {%0,%1,%2,%3};"
                 : "+f"(c[0]), "+f"(c[1]), "+f"(c[2]), "+f"(c[3])
                 : "r"(a0), "r"(a1), "r"(a2), "r"(a3), "r"(b0), "r"(b1));
}

__device__ __forceinline__ float ftanh(float x) {
    float e = __expf(2.0f * x);
    return 1.0f - __fdividef(2.0f, e + 1.0f);
}

__device__ __forceinline__ void cvt_store8(const float4* s4, uint2* d2) {
    float4 x[8];
#pragma unroll
    for (int i = 0; i < 8; i++) x[i] = s4[i * 256];
#pragma unroll
    for (int i = 0; i < 8; i++) {
        __half2 h0 = __floats2half2_rn(x[i].x, x[i].y);
        __half2 h1 = __floats2half2_rn(x[i].z, x[i].w);
        d2[i * 256] = make_uint2(*(uint32_t*)&h0, *(uint32_t*)&h1);
    }
}

// ---------------------------------------------------------------------------
// prologue kernels (separate launches — measured faster than fused)
// ---------------------------------------------------------------------------
#define W_ELEMS      (512 * 512)
#define BATCH_F4     (SRCN * DIM / 4)            // 131072 float4 per batch
#define C0_ELEMS     ((size_t)C0B * SRCN * DIM)  // 8388608

__global__ void __launch_bounds__(256) convert_w_kernel(const float* __restrict__ W_ref,
                                                        const float* __restrict__ conv_w) {
    size_t w8 = ((size_t)blockIdx.x * 256 + threadIdx.x) * 8;
    const float* wsrc = (w8 < W_ELEMS) ? (W_ref + w8) : (conv_w + (w8 - W_ELEMS));
    float4 x0 = *reinterpret_cast<const float4*>(wsrc);
    float4 x1 = *reinterpret_cast<const float4*>(wsrc + 4);
    __half2 h0 = __floats2half2_rn(x0.x, x0.y);
    __half2 h1 = __floats2half2_rn(x0.z, x0.w);
    __half2 h2 = __floats2half2_rn(x1.x, x1.y);
    __half2 h3 = __floats2half2_rn(x1.z, x1.w);
    uint4 o = make_uint4(*(uint32_t*)&h0, *(uint32_t*)&h1, *(uint32_t*)&h2, *(uint32_t*)&h3);
    *reinterpret_cast<uint4*>(g_w16 + w8) = o;
}

__global__ void __launch_bounds__(256) convert_src_kernel(const float* __restrict__ src) {
    size_t i8 = ((size_t)blockIdx.x * 256 + threadIdx.x) * 8;
    float4 x0 = *reinterpret_cast<const float4*>(src + i8);
    float4 x1 = *reinterpret_cast<const float4*>(src + i8 + 4);
    __half2 h0 = __floats2half2_rn(x0.x, x0.y);
    __half2 h1 = __floats2half2_rn(x0.z, x0.w);
    __half2 h2 = __floats2half2_rn(x1.x, x1.y);
    __half2 h3 = __floats2half2_rn(x1.z, x1.w);
    uint4 o = make_uint4(*(uint32_t*)&h0, *(uint32_t*)&h1, *(uint32_t*)&h2, *(uint32_t*)&h3);
    *reinterpret_cast<uint4*>(g_src16 + i8) = o;
}

__global__ void __launch_bounds__(512) qproj_kernel(const float* __restrict__ tgt,
                                                    const float* __restrict__ Wq) {
    __shared__ float st[4 * DIM];
    const int b0 = blockIdx.x * 4;
    const int tid = threadIdx.x;
    for (int i = tid; i < 4 * DIM; i += 512) st[i] = tgt[(size_t)b0 * DIM + i];
    __syncthreads();
    const float4* w = reinterpret_cast<const float4*>(Wq + (size_t)tid * DIM);
    const float4* t0 = reinterpret_cast<const float4*>(st);
    const float4* t1 = reinterpret_cast<const float4*>(st + DIM);
    const float4* t2 = reinterpret_cast<const float4*>(st + 2 * DIM);
    const float4* t3 = reinterpret_cast<const float4*>(st + 3 * DIM);
    float a0 = 0.f, a1 = 0.f, a2 = 0.f, a3 = 0.f;
#pragma unroll 4
    for (int i = 0; i < DIM / 4; i++) {
        float4 wv = w[i];
        float4 c;
        c = t0[i]; a0 += wv.x*c.x + wv.y*c.y + wv.z*c.z + wv.w*c.w;
        c = t1[i]; a1 += wv.x*c.x + wv.y*c.y + wv.z*c.z + wv.w*c.w;
        c = t2[i]; a2 += wv.x*c.x + wv.y*c.y + wv.z*c.z + wv.w*c.w;
        c = t3[i]; a3 += wv.x*c.x + wv.y*c.y + wv.z*c.z + wv.w*c.w;
    }
    g_q_buf[(size_t)(b0 + 0) * DIM + tid] = a0;
    g_q_buf[(size_t)(b0 + 1) * DIM + tid] = a1;
    g_q_buf[(size_t)(b0 + 2) * DIM + tid] = a2;
    g_q_buf[(size_t)(b0 + 3) * DIM + tid] = a3;
}

// ---------------------------------------------------------------------------
// main GEMM (R5 mainloop): per CTA 128(M=s) x 128(N=e/o), K=512
// K-tile 64, 3 stages of 32KB, 2 CTAs/SM.
// Prelude: convert conv_ratio slices of the NEXT chunk's src.
// grid: (64, chunk_batches): y = batch within chunk, x = nt*8 + mt
// ---------------------------------------------------------------------------
#define KT          64
#define NKT         8
#define STAGES      3
#define STAGE_BYTES 32768
#define C_PITCH     132
#define SM_QV       (STAGES * STAGE_BYTES)       // 98304
#define SMEM_TOTAL  (SM_QV + 1024)               // 99328

extern __shared__ char dsm[];

__global__ void __launch_bounds__(256, 2)
gemm_kernel(const float* __restrict__ conv_b,
            const float* __restrict__ v,
            const float* __restrict__ src32,
            float* __restrict__ out_attn,
            int b_off, int conv_batch_start, int conv_ratio) {
    const uint32_t smb = smem_u32(dsm);
    const int tid  = threadIdx.x;
    const int wid  = tid >> 5;
    const int lane = tid & 31;
    const int wm   = wid & 3;
    const int wn   = wid >> 2;

    const int b  = b_off + blockIdx.y;
    const int nt = blockIdx.x >> 3;
    const int mt = blockIdx.x & 7;
    const int s0 = mt * 128;
    const int n0 = nt * 128;
    const bool is_ref = (nt < 4);

    float* sQ = reinterpret_cast<float*>(dsm + SM_QV);
    float* sV = reinterpret_cast<float*>(dsm + SM_QV + 512);
    float* sC = reinterpret_cast<float*>(dsm);

    if (tid < 128) {
        if (is_ref) {
            sQ[tid] = g_q_buf[(size_t)b * DIM + n0 + tid];
            sV[tid] = v[n0 + tid];
        } else {
            sQ[tid] = conv_b[(n0 - 512) + tid];
        }
    }

    const __half* gA = g_src16 + ((size_t)b * SRCN + s0) * DIM;
    const __half* gB = g_w16 + (size_t)n0 * DIM;

    const int crow = tid >> 3;
    const int ccol = tid & 7;

    const int a_rl = lane & 15;
    const int a_ch = lane >> 4;
    const int b_rl = (lane & 7) | (((lane >> 4) & 1) << 3);
    const int b_ch = (lane >> 3) & 1;

    const int arow0 = wm * 32 + a_rl;
    const int arow1 = arow0 + 16;
    const int ax0 = arow0 & 7;
    const int ax1 = arow1 & 7;
    const int brow0 = wn * 64 + b_rl;

    auto load_stage = [&](int st, int kt) {
        uint32_t base = smb + st * STAGE_BYTES;
        const __half* ga = gA + kt * KT;
        const __half* gb = gB + kt * KT;
#pragma unroll
        for (int p = 0; p < 4; p++) {
            int r = crow + p * 32;
            int swc = ccol ^ (r & 7);
            CP_ASYNC16(base + r * 128 + swc * 16, ga + (size_t)r * DIM + ccol * 8);
        }
#pragma unroll
        for (int p = 0; p < 4; p++) {
            int r = crow + p * 32;
            int swc = ccol ^ (r & 7);
            CP_ASYNC16(base + 16384 + r * 128 + swc * 16, gb + (size_t)r * DIM + ccol * 8);
        }
    };

    load_stage(0, 0); CP_COMMIT();
    load_stage(1, 1); CP_COMMIT();

    // ---- convert prelude: conv_ratio slices of the next chunk's src ----
    if (conv_ratio > 0) {
        const int cta = blockIdx.y * 64 + blockIdx.x;
        size_t base_f4 = (size_t)conv_batch_start * BATCH_F4;
#pragma unroll 1
        for (int k = 0; k < conv_ratio; k++) {
            size_t f4 = base_f4 + ((size_t)cta * conv_ratio + k) * 2048 + tid;
            cvt_store8(reinterpret_cast<const float4*>(src32) + f4,
                       reinterpret_cast<uint2*>(g_src16) + f4);
        }
    }

    float cacc[2][8][4];
#pragma unroll
    for (int i = 0; i < 2; i++)
#pragma unroll
        for (int j = 0; j < 8; j++)
#pragma unroll
            for (int r = 0; r < 4; r++) cacc[i][j][r] = 0.f;

    uint32_t a[2][4];
    uint32_t bb[4][4];

    for (int kt = 0; kt < NKT; kt++) {
        CP_WAIT1();
        __syncthreads();
        if (kt + 2 < NKT) load_stage((kt + 2) % 3, kt + 2);
        CP_COMMIT();

        uint32_t abase = smb + (kt % 3) * STAGE_BYTES;
        uint32_t bbase = abase + 16384;

#pragma unroll
        for (int kk = 0; kk < 4; kk++) {
            {
                int c0 = (kk * 2 + a_ch) ^ ax0;
                ldsm4(a[0][0], a[0][1], a[0][2], a[0][3], abase + arow0 * 128 + c0 * 16);
                int c1 = (kk * 2 + a_ch) ^ ax1;
                ldsm4(a[1][0], a[1][1], a[1][2], a[1][3], abase + arow1 * 128 + c1 * 16);
            }
#pragma unroll
            for (int jj = 0; jj < 4; jj++) {
                int brow = brow0 + jj * 16;
                int c = (kk * 2 + b_ch) ^ (brow & 7);
                ldsm4(bb[jj][0], bb[jj][1], bb[jj][2], bb[jj][3], bbase + brow * 128 + c * 16);
            }
#pragma unroll
            for (int i = 0; i < 2; i++)
#pragma unroll
                for (int j = 0; j < 8; j++) {
                    int jj = j >> 1;
                    if (j & 1)
                        mma_f16(cacc[i][j], a[i][0], a[i][1], a[i][2], a[i][3], bb[jj][2], bb[jj][3]);
                    else
                        mma_f16(cacc[i][j], a[i][0], a[i][1], a[i][2], a[i][3], bb[jj][0], bb[jj][1]);
                }
        }
    }

    // ------------------------- epilogues -------------------------
    if (is_ref) {
        const int q = lane >> 2;
        const int cl = (lane & 3) * 2;
#pragma unroll
        for (int i = 0; i < 2; i++) {
            float p0 = 0.f, p1 = 0.f;
#pragma unroll
            for (int j = 0; j < 8; j++) {
                int el = wn * 64 + j * 8 + cl;
                float v0 = sV[el], v1 = sV[el + 1];
                float q0 = sQ[el], q1 = sQ[el + 1];
                p0 += v0 * ftanh(q0 + cacc[i][j][0]) + v1 * ftanh(q1 + cacc[i][j][1]);
                p1 += v0 * ftanh(q0 + cacc[i][j][2]) + v1 * ftanh(q1 + cacc[i][j][3]);
            }
            p0 += __shfl_xor_sync(0xffffffffu, p0, 1);
            p0 += __shfl_xor_sync(0xffffffffu, p0, 2);
            p1 += __shfl_xor_sync(0xffffffffu, p1, 1);
            p1 += __shfl_xor_sync(0xffffffffu, p1, 2);
            if ((lane & 3) == 0) {
                int r0 = wm * 32 + i * 16 + q;
                size_t idx = (((size_t)b * SRCN + s0 + r0) << 3) + nt * 2 + wn;
                g_u_part[idx] = p0;
                g_u_part[idx + (8ull << 3)] = p1;
            }
        }
    } else {
        const int q = lane >> 2;
        const int cl = (lane & 3) * 2;
        const int o0 = n0 - 512;
        float* outb = out_attn + ((size_t)b * DIM + o0) * SRCN + s0;
#pragma unroll
        for (int h = 0; h < 2; h++) {
            __syncthreads();
            if (wn == h) {
#pragma unroll
                for (int i = 0; i < 2; i++) {
                    int r0 = wm * 32 + i * 16 + q;
#pragma unroll
                    for (int j = 0; j < 8; j++) {
                        int o = j * 8 + cl;
                        sC[o * C_PITCH + r0]           = cacc[i][j][0];
                        sC[(o + 1) * C_PITCH + r0]     = cacc[i][j][1];
                        sC[o * C_PITCH + r0 + 8]       = cacc[i][j][2];
                        sC[(o + 1) * C_PITCH + r0 + 8] = cacc[i][j][3];
                    }
                }
            }
            __syncthreads();
#pragma unroll 2
            for (int it = tid; it < 64 * 32; it += 256) {
                int o = it >> 5;
                int sq = (it & 31) * 4;
                float4 val = *reinterpret_cast<const float4*>(sC + o * C_PITCH + sq);
                float bias = sQ[h * 64 + o];
                val.x += bias; val.y += bias; val.z += bias; val.w += bias;
                *reinterpret_cast<float4*>(outb + (size_t)(h * 64 + o) * SRCN + sq) = val;
            }
        }
    }
}

// ---------------------------------------------------------------------------
// softmax: u = sum(8 partials); score=C*tanh(u); mask; softmax; outputs
// ---------------------------------------------------------------------------
__global__ void softmax_kernel(const uint8_t* __restrict__ mask_in,
                               const int* __restrict__ prev,
                               float* __restrict__ out,
                               int has_logits, int has_mask) {
    __shared__ float red[256];
    const int b = blockIdx.x, tid = threadIdx.x;
    const int p = prev[b];

    float sc[4];
    bool  ms[4];
    float mx = -3.0e38f;
#pragma unroll
    for (int j = 0; j < 4; j++) {
        int s = tid + j * 256;
        const float* up = g_u_part + (((size_t)b * SRCN + s) << 3);
        float u = 0.f;
#pragma unroll
        for (int k = 0; k < 8; k++) u += up[k];
        bool m = (mask_in[(size_t)b * SRCN + s] != 0) || (s == p);
        ms[j] = m;
        float val = m ? -3.0e38f : 10.f * tanhf(u);
        sc[j] = val;
        mx = fmaxf(mx, val);
    }
    red[tid] = mx; __syncthreads();
    for (int o = 128; o > 0; o >>= 1) {
        if (tid < o) red[tid] = fmaxf(red[tid], red[tid + o]);
        __syncthreads();
    }
    mx = red[0];
    __syncthreads();

    float e[4], se = 0.f;
#pragma unroll
    for (int j = 0; j < 4; j++) {
        e[j] = ms[j] ? 0.f : expf(sc[j] - mx);
        se += e[j];
    }
    red[tid] = se; __syncthreads();
    for (int o = 128; o > 0; o >>= 1) {
        if (tid < o) red[tid] += red[tid + o];
        __syncthreads();
    }
    const float inv = 1.f / red[0];

    const size_t attn = (size_t)BZ * DIM * SRCN;
#pragma unroll
    for (int j = 0; j < 4; j++) {
        int s = tid + j * 256;
        if (has_logits) out[attn + (size_t)b * SRCN + s] = e[j] * inv;
        if (has_mask)   out[attn + (size_t)BZ * SRCN + (size_t)b * SRCN + s] = ms[j] ? 1.f : 0.f;
    }
}

// ---------------------------------------------------------------------------
extern "C" void kernel_launch(void* const* d_in, const int* in_sizes, int n_in,
                              void* d_out, int out_size) {
    (void)in_sizes; (void)n_in;
    const float*   src    = (const float*)d_in[0];
    const float*   tgt    = (const float*)d_in[1];
    const uint8_t* mask   = (const uint8_t*)d_in[2];
    const int*     prev   = (const int*)d_in[3];
    const float*   W_q    = (const float*)d_in[4];
    const float*   W_ref  = (const float*)d_in[5];
    const float*   v      = (const float*)d_in[6];
    const float*   conv_w = (const float*)d_in[7];
    const float*   conv_b = (const float*)d_in[8];
    float* out = (float*)d_out;

    const size_t attn = (size_t)BZ * DIM * SRCN;
    const size_t row  = (size_t)BZ * SRCN;
    int has_logits = ((size_t)out_size >= attn + row)     ? 1 : 0;
    int has_mask   = ((size_t)out_size >= attn + 2 * row) ? 1 : 0;

    cudaFuncSetAttribute(gemm_kernel,
                         cudaFuncAttributeMaxDynamicSharedMemorySize, SMEM_TOTAL);

    // prologue: weight convert, qproj, chunk-0 (16 batches) src convert
    convert_w_kernel<<<256, 256>>>(W_ref, conv_w);
    qproj_kernel<<<64, 512>>>(tgt, W_q);
    convert_src_kernel<<<(int)(C0_ELEMS / 8 / 256), 256>>>(src);

    // chunked GEMM, non-uniform {16,48,96,96}; chunk c preludes chunk c+1
    dim3 g0(64, C0B), g1(64, C1B), g2(64, C2B), g3(64, C3B);
    gemm_kernel<<<g0, 256, SMEM_TOTAL>>>(conv_b, v, src, out, 0,                 C0B,             3);
    gemm_kernel<<<g1, 256, SMEM_TOTAL>>>(conv_b, v, src, out, C0B,               C0B + C1B,       2);
    gemm_kernel<<<g2, 256, SMEM_TOTAL>>>(conv_b, v, src, out, C0B + C1B,         C0B + C1B + C2B, 1);
    gemm_kernel<<<g3, 256, SMEM_TOTAL>>>(conv_b, v, src, out, C0B + C1B + C2B,   0,               0);

    softmax_kernel<<<BZ, 256>>>(mask, prev, out, has_logits, has_mask);
}